// round 11
// baseline (speedup 1.0000x reference)
#include <cuda_runtime.h>
#include <cstdint>
#include <math.h>

#define BB 8
#define SS 2048
#define EE 1024
#define DD 64
#define NSEG 3              // split-KV segments

// q (all rows, scattered) and k,v (COMPACTED rows) as bf16 hi/lo planes
__device__ unsigned int g_qh[BB * SS * DD / 2];
__device__ unsigned int g_ql[BB * SS * DD / 2];
__device__ unsigned int g_kh[BB * SS * DD / 2];
__device__ unsigned int g_kl[BB * SS * DD / 2];
__device__ unsigned int g_vh[BB * SS * DD / 2];
__device__ unsigned int g_vl[BB * SS * DD / 2];

// W planes (bf16 hi/lo), [mat][n][k/2] u32
__device__ unsigned int g_Wh[3 * 64 * 512];
__device__ unsigned int g_Wl[3 * 64 * 512];

// mask compaction: unmasked list, masked list, unmasked count
__device__ int g_kidx[BB][SS];
__device__ int g_midx[BB][SS];
__device__ int g_kcnt[BB];

// split-KV partials
__device__ float g_Op[NSEG][BB * SS * DD];
__device__ float g_mp[NSEG][BB * SS];
__device__ float g_lp[NSEG][BB * SS];

// ---------------------------------------------------------------------------
// helpers
// ---------------------------------------------------------------------------
__device__ __forceinline__ uint32_t smem_u32(const void* p) {
    return (uint32_t)__cvta_generic_to_shared(p);
}

__device__ __forceinline__ void ldsm_x4(uint32_t addr, uint32_t& r0, uint32_t& r1,
                                        uint32_t& r2, uint32_t& r3) {
    asm volatile("ldmatrix.sync.aligned.m8n8.x4.shared.b16 {%0,%1,%2,%3}, [%4];"
                 : "=r"(r0), "=r"(r1), "=r"(r2), "=r"(r3) : "r"(addr));
}

__device__ __forceinline__ void ldsm_x4_t(uint32_t addr, uint32_t& r0, uint32_t& r1,
                                          uint32_t& r2, uint32_t& r3) {
    asm volatile("ldmatrix.sync.aligned.m8n8.x4.trans.shared.b16 {%0,%1,%2,%3}, [%4];"
                 : "=r"(r0), "=r"(r1), "=r"(r2), "=r"(r3) : "r"(addr));
}

__device__ __forceinline__ void mma_bf16(float c[4],
                                         uint32_t a0, uint32_t a1, uint32_t a2, uint32_t a3,
                                         uint32_t b0, uint32_t b1) {
    asm volatile("mma.sync.aligned.m16n8k16.row.col.f32.bf16.bf16.f32 "
                 "{%0,%1,%2,%3}, {%4,%5,%6,%7}, {%8,%9}, {%0,%1,%2,%3};"
                 : "+f"(c[0]), "+f"(c[1]), "+f"(c[2]), "+f"(c[3])
                 : "r"(a0), "r"(a1), "r"(a2), "r"(a3), "r"(b0), "r"(b1));
}

__device__ __forceinline__ uint32_t pack2(float x0, float x1) {
    uint32_t h;
    asm("cvt.rn.bf16x2.f32 %0, %1, %2;" : "=r"(h) : "f"(x1), "f"(x0));
    return h;
}

__device__ __forceinline__ void split_pair(float x0, float x1, uint32_t& hi, uint32_t& lo) {
    hi = pack2(x0, x1);
    float h0 = __uint_as_float(hi << 16);
    float h1 = __uint_as_float(hi & 0xffff0000u);
    lo = pack2(x0 - h0, x1 - h1);
}

__device__ __forceinline__ void cp16(uint32_t s, const void* g) {
    asm volatile("cp.async.cg.shared.global [%0], [%1], 16;" :: "r"(s), "l"(g));
}

// ---------------------------------------------------------------------------
// prep kernels
// ---------------------------------------------------------------------------
__global__ void prep_w(const float* __restrict__ Wq, const float* __restrict__ Wk,
                       const float* __restrict__ Wv) {
    int idx = blockIdx.x * 256 + threadIdx.x;
    int mat = idx >> 15;
    int off = idx & 32767;
    const float* W = (mat == 0) ? Wq : (mat == 1) ? Wk : Wv;
    float2 v = reinterpret_cast<const float2*>(W)[off];
    uint32_t h, l;
    split_pair(v.x, v.y, h, l);
    g_Wh[idx] = h;
    g_Wl[idx] = l;
}

__global__ void prep_mask(const int* __restrict__ mask) {
    const int b = blockIdx.x;
    const int t = threadIdx.x;
    __shared__ int wsum[8];
    const int* mrow = mask + (size_t)b * SS;

    int um[8], loc[8], cnt = 0;
    #pragma unroll
    for (int j = 0; j < 8; j++) {
        int s = t * 8 + j;
        um[j] = (mrow[s] == 0);
        loc[j] = cnt;
        cnt += um[j];
    }
    const int lane = t & 31, w = t >> 5;
    int inc = cnt;
    #pragma unroll
    for (int off = 1; off < 32; off <<= 1) {
        int n = __shfl_up_sync(0xffffffffu, inc, off);
        if (lane >= off) inc += n;
    }
    if (lane == 31) wsum[w] = inc;
    __syncthreads();
    int wbase = 0;
    #pragma unroll
    for (int i = 0; i < 8; i++)
        if (i < w) wbase += wsum[i];
    const int base = wbase + inc - cnt;
    #pragma unroll
    for (int j = 0; j < 8; j++) {
        int s = t * 8 + j;
        int u = base + loc[j];          // unmasked strictly before s
        if (um[j]) g_kidx[b][u] = s;
        else       g_midx[b][s - u] = s;
    }
    if (t == 255) g_kcnt[b] = base + cnt;
}

// ---------------------------------------------------------------------------
// Projection body, templated on NMAT.
//   NMAT=3: gathered UNMASKED rows -> Q (scattered to orig rows) + K,V (compact)
//   NMAT=1: gathered MASKED rows   -> Q only (scattered to orig rows)
// BM=64, BK=32, 256 threads (8 warps: 4 M x 2 N). W planes via cp.async
// double-buffer; x rows via 2-DEEP parity-paired f32 register prefetch
// (LDG for slab i+3 issued at iter i -> ~2 slab-times of DRAM latency cover).
// ---------------------------------------------------------------------------
#define QP 40
#define XPL (64 * QP)            // u16 per plane
#define XSTG (2 * XPL)
#define WBASE (2 * XSTG)
#define PROJ_SMEM_BYTES ((WBASE + 2 * 6 * XPL) * 2)   // sized for NMAT=3

template<int NMAT>
__device__ __forceinline__ void proj_body(
    unsigned short* qsm, const float* __restrict__ x,
    const float* __restrict__ bq, const float* __restrict__ bk,
    const float* __restrict__ bv,
    int b, int j0, int cnt, const int* __restrict__ list)
{
    constexpr int WSTGP = 2 * NMAT;

    const int t = threadIdx.x;
    const int warp = t >> 5, lane = t & 31;
    const int wm = warp >> 1;
    const int wn = warp & 1;

    float acc[NMAT][4][4] = {};

    const int arow = wm * 16 + (lane & 15);
    const int acol = (lane >> 4) * 8;
    const int brow = (lane & 7) + ((lane >> 4) << 3);
    const int bcol = ((lane >> 3) & 1) * 8;

    const int xr = t >> 2;             // staged row within tile
    const int xc = (t & 3) * 8;        // f32 col base

    // gather source row (clamped tail -> duplicate rows, consistent outputs)
    int jg = j0 + xr;
    if (jg > cnt - 1) jg = cnt - 1;
    const float* xrow = x + ((size_t)b * SS + list[jg]) * EE;

    // W stage s for k-slab: 2*NMAT planes x 256 chunks of 16B (proven map)
    auto issue_w = [&](int s, int slab) {
        #pragma unroll
        for (int i = 0; i < 2 * NMAT; i++) {
            int chunk = t + i * 256;
            int p = chunk >> 8, c = chunk & 255;
            int row = c >> 2, c4 = c & 3;
            uint32_t dst = smem_u32(&qsm[WBASE + (s * WSTGP + p) * XPL + row * QP + c4 * 8]);
            const unsigned int* srcp = (p & 1) ? g_Wl : g_Wh;
            cp16(dst, srcp + ((size_t)(p >> 1) * 32768
                              + (size_t)row * 512 + slab * 16 + c4 * 4));
        }
        asm volatile("cp.async.commit_group;");
    };

    auto sts_x = [&](int s, float4 a0, float4 a1) {
        unsigned short* Xh = qsm + s * XSTG;
        unsigned short* Xl = Xh + XPL;
        uint32_t h, l;
        split_pair(a0.x, a0.y, h, l);
        *(uint32_t*)&Xh[xr * QP + xc]     = h; *(uint32_t*)&Xl[xr * QP + xc]     = l;
        split_pair(a0.z, a0.w, h, l);
        *(uint32_t*)&Xh[xr * QP + xc + 2] = h; *(uint32_t*)&Xl[xr * QP + xc + 2] = l;
        split_pair(a1.x, a1.y, h, l);
        *(uint32_t*)&Xh[xr * QP + xc + 4] = h; *(uint32_t*)&Xl[xr * QP + xc + 4] = l;
        split_pair(a1.z, a1.w, h, l);
        *(uint32_t*)&Xh[xr * QP + xc + 6] = h; *(uint32_t*)&Xl[xr * QP + xc + 6] = l;
    };

    const int NI = EE / 32;   // 32 slabs

    issue_w(0, 0);
    {   // slab 0 staged directly
        float4 a0 = *reinterpret_cast<const float4*>(&xrow[xc]);
        float4 a1 = *reinterpret_cast<const float4*>(&xrow[xc + 4]);
        sts_x(0, a0, a1);
    }
    // parity prefetch sets: A holds odd slabs (1,3,..), B holds even (2,4,..)
    float4 xA0 = *reinterpret_cast<const float4*>(&xrow[32 + xc]);
    float4 xA1 = *reinterpret_cast<const float4*>(&xrow[32 + xc + 4]);
    float4 xB0 = *reinterpret_cast<const float4*>(&xrow[64 + xc]);
    float4 xB1 = *reinterpret_cast<const float4*>(&xrow[64 + xc + 4]);

    for (int i = 0; i < NI; i++) {
        const int s = i & 1;

        asm volatile("cp.async.wait_group 0;");
        __syncthreads();

        if (i + 1 < NI) {
            issue_w(s ^ 1, i + 1);
            if ((s ^ 1) == 1) {          // slab i+1 odd -> set A
                sts_x(1, xA0, xA1);
                if (i + 3 < NI) {
                    int kn = (i + 3) * 32;
                    xA0 = *reinterpret_cast<const float4*>(&xrow[kn + xc]);
                    xA1 = *reinterpret_cast<const float4*>(&xrow[kn + xc + 4]);
                }
            } else {                     // slab i+1 even -> set B
                sts_x(0, xB0, xB1);
                if (i + 3 < NI) {
                    int kn = (i + 3) * 32;
                    xB0 = *reinterpret_cast<const float4*>(&xrow[kn + xc]);
                    xB1 = *reinterpret_cast<const float4*>(&xrow[kn + xc + 4]);
                }
            }
        }

        const unsigned short* Xh = qsm + s * XSTG;
        const unsigned short* Xl = Xh + XPL;
        const unsigned short* Wb = qsm + WBASE + s * WSTGP * XPL;

        #pragma unroll
        for (int ks = 0; ks < 2; ks++) {
            uint32_t ah[4], al[4];
            ldsm_x4(smem_u32(&Xh[arow * QP + ks * 16 + acol]), ah[0], ah[1], ah[2], ah[3]);
            ldsm_x4(smem_u32(&Xl[arow * QP + ks * 16 + acol]), al[0], al[1], al[2], al[3]);
            #pragma unroll
            for (int mm = 0; mm < NMAT; mm++) {
                const unsigned short* Wh = Wb + (mm * 2) * XPL;
                const unsigned short* Wl = Wh + XPL;
                #pragma unroll
                for (int pr = 0; pr < 2; pr++) {
                    uint32_t bh0, bh1, bh2, bh3, bl0, bl1, bl2, bl3;
                    ldsm_x4(smem_u32(&Wh[(wn * 32 + pr * 16 + brow) * QP + ks * 16 + bcol]),
                            bh0, bh1, bh2, bh3);
                    ldsm_x4(smem_u32(&Wl[(wn * 32 + pr * 16 + brow) * QP + ks * 16 + bcol]),
                            bl0, bl1, bl2, bl3);
                    float* c0 = acc[mm][pr * 2];
                    float* c1 = acc[mm][pr * 2 + 1];
                    mma_bf16(c0, ah[0], ah[1], ah[2], ah[3], bh0, bh1);
                    mma_bf16(c0, ah[0], ah[1], ah[2], ah[3], bl0, bl1);
                    mma_bf16(c0, al[0], al[1], al[2], al[3], bh0, bh1);
                    mma_bf16(c1, ah[0], ah[1], ah[2], ah[3], bh2, bh3);
                    mma_bf16(c1, ah[0], ah[1], ah[2], ah[3], bl2, bl3);
                    mma_bf16(c1, al[0], al[1], al[2], al[3], bh2, bh3);
                }
            }
        }
    }

    // epilogue: Q (mm=0) scattered to original rows; K/V (mm=1,2) compacted
    int jr0 = j0 + wm * 16 + (lane >> 2);
    int jr8 = jr0 + 8;
    if (jr0 > cnt - 1) jr0 = cnt - 1;
    if (jr8 > cnt - 1) jr8 = cnt - 1;
    const size_t qrow0 = (size_t)b * SS + list[jr0];
    const size_t qrow8 = (size_t)b * SS + list[jr8];

    #pragma unroll
    for (int mm = 0; mm < NMAT; mm++) {
        const float* bias = (mm == 0) ? bq : (mm == 1) ? bk : bv;
        unsigned int* gh = (mm == 0) ? g_qh : (mm == 1) ? g_kh : g_vh;
        unsigned int* gl = (mm == 0) ? g_ql : (mm == 1) ? g_kl : g_vl;
        size_t r0, r8;
        if (mm == 0) { r0 = qrow0; r8 = qrow8; }
        else {
            r0 = (size_t)b * SS + j0 + wm * 16 + (lane >> 2);
            r8 = r0 + 8;
        }
        #pragma unroll
        for (int na = 0; na < 4; na++) {
            int col = wn * 32 + na * 8 + (lane & 3) * 2;
            float b0 = bias[col], b1 = bias[col + 1];
            float c0 = acc[mm][na][0] + b0, c1 = acc[mm][na][1] + b1;
            float c2 = acc[mm][na][2] + b0, c3 = acc[mm][na][3] + b1;
            uint32_t h, l;
            split_pair(c0, c1, h, l);
            gh[r0 * 32 + col / 2] = h;
            gl[r0 * 32 + col / 2] = l;
            split_pair(c2, c3, h, l);
            gh[r8 * 32 + col / 2] = h;
            gl[r8 * 32 + col / 2] = l;
        }
    }
}

__global__ __launch_bounds__(256, 2) void proj_kernel(
    const float* __restrict__ x,
    const float* __restrict__ bq, const float* __restrict__ bk,
    const float* __restrict__ bv)
{
    extern __shared__ unsigned short qsm[];
    const int b = blockIdx.y;
    const int j0 = blockIdx.x * 64;
    const int nk = g_kcnt[b];

    if (blockIdx.z == 0) {
        if (j0 >= nk) return;
        proj_body<3>(qsm, x, bq, bk, bv, b, j0, nk, g_kidx[b]);
    } else {
        const int nm = SS - nk;
        if (j0 >= nm || nm == 0) return;
        proj_body<1>(qsm, x, bq, bk, bv, b, j0, nm, g_midx[b]);
    }
}

// ---------------------------------------------------------------------------
// Flash attention over COMPACTED keys (contiguous), split-KV x3.
// (unchanged — proven at 46.1us)
// ---------------------------------------------------------------------------
#define KP 72
#define TILE_U16 (64 * KP)
#define STAGE_U16 (4 * TILE_U16)
#define ATTN_SMEM_BYTES (2 * STAGE_U16 * 2 + 64 * 4)

__device__ __forceinline__ void stage_tile(uint32_t sbase, size_t gbase, int t) {
    #pragma unroll
    for (int i = 0; i < 4; i++) {
        int chunk = t + i * 128;
        int r = chunk >> 3, c = chunk & 7;
        uint32_t soff = (uint32_t)(r * KP + c * 8) * 2;
        size_t goff = (size_t)r * 32 + c * 4;
        cp16(sbase + soff,                     g_kh + gbase + goff);
        cp16(sbase + TILE_U16 * 2 + soff,      g_kl + gbase + goff);
        cp16(sbase + 2 * TILE_U16 * 2 + soff,  g_vh + gbase + goff);
        cp16(sbase + 3 * TILE_U16 * 2 + soff,  g_vl + gbase + goff);
    }
    asm volatile("cp.async.commit_group;");
}

__global__ __launch_bounds__(128, 3) void attn_kernel()
{
    extern __shared__ unsigned short sm[];
    float* ms = (float*)(sm + 2 * STAGE_U16);

    const int t = threadIdx.x, warp = t >> 5, lane = t & 31;
    const int b = blockIdx.y, q0 = blockIdx.x * 64;
    const int seg = blockIdx.z;

    const int nk = g_kcnt[b];
    const int T = (nk + 63) >> 6;
    const int bnt = T / 3, rem = T - bnt * 3;
    const int nt = bnt + (seg < rem ? 1 : 0);
    const int t0 = seg * bnt + (seg < rem ? seg : rem);

    // --- stage Q into stage-0, extract fragments ---
    {
        uint32_t s0 = smem_u32(sm);
        size_t gq = ((size_t)b * SS + q0) * 32;
        #pragma unroll
        for (int i = 0; i < 4; i++) {
            int chunk = t + i * 128;
            int r = chunk >> 3, c = chunk & 7;
            uint32_t soff = (uint32_t)(r * KP + c * 8) * 2;
            size_t goff = (size_t)r * 32 + c * 4;
            cp16(s0 + soff,                g_qh + gq + goff);
            cp16(s0 + TILE_U16 * 2 + soff, g_ql + gq + goff);
        }
        asm volatile("cp.async.commit_group;");
        asm volatile("cp.async.wait_group 0;");
        __syncthreads();
    }

    uint32_t qh[4][4], ql[4][4];
    {
        const int arow = warp * 16 + (lane & 15);
        const int acol = (lane >> 4) * 8;
        #pragma unroll
        for (int ks = 0; ks < 4; ks++) {
            ldsm_x4(smem_u32(&sm[arow * KP + ks * 16 + acol]),
                    qh[ks][0], qh[ks][1], qh[ks][2], qh[ks][3]);
            ldsm_x4(smem_u32(&sm[TILE_U16 + arow * KP + ks * 16 + acol]),
                    ql[ks][0], ql[ks][1], ql[ks][2], ql[ks][3]);
        }
    }
    __syncthreads();

    float O[8][4] = {};
    float m0r = -INFINITY, m1r = -INFINITY, l0r = 0.f, l1r = 0.f;
    const float scale = 0.125f;

    const uint32_t stage_addr[2] = { smem_u32(sm), smem_u32(sm + STAGE_U16) };

    if (nt > 0) {
        stage_tile(stage_addr[0], ((size_t)b * SS + t0 * 64) * 32, t);

        const int brow = (lane & 7) + ((lane >> 4) << 3);
        const int bco  = ((lane >> 3) & 1) * 8;
        const int vrow = lane & 15;
        const int vco  = (lane >> 4) * 8;

        for (int it = 0; it < nt; ++it) {
            const int st = it & 1;
            const unsigned short* Kh = sm + st * STAGE_U16;
            const unsigned short* Kl = Kh + TILE_U16;
            const unsigned short* Vh = Kh + 2 * TILE_U16;
            const unsigned short* Vl = Kh + 3 * TILE_U16;

            if (it + 1 < nt)
                stage_tile(stage_addr[st ^ 1], ((size_t)b * SS + (t0 + it + 1) * 64) * 32, t);
            if (t < 64) ms[t] = ((t0 + it) * 64 + t < nk) ? 0.f : -INFINITY;

            if (it + 1 < nt) asm volatile("cp.async.wait_group 1;");
            else             asm volatile("cp.async.wait_group 0;");
            __syncthreads();

            // --- S = Q K^T ---
            float S[8][4] = {};
            #pragma unroll
            for (int ks = 0; ks < 4; ks++) {
                #pragma unroll
                for (int pr = 0; pr < 4; pr++) {
                    uint32_t bh0, bh1, bh2, bh3, bl0, bl1, bl2, bl3;
                    ldsm_x4(smem_u32(&Kh[(pr * 16 + brow) * KP + ks * 16 + bco]),
                            bh0, bh1, bh2, bh3);
                    ldsm_x4(smem_u32(&Kl[(pr * 16 + brow) * KP + ks * 16 + bco]),
                            bl0, bl1, bl2, bl3);
                    float* s0 = S[pr * 2];
                    float* s1 = S[pr * 2 + 1];
                    mma_bf16(s0, qh[ks][0], qh[ks][1], qh[ks][2], qh[ks][3], bh0, bh1);
                    mma_bf16(s0, qh[ks][0], qh[ks][1], qh[ks][2], qh[ks][3], bl0, bl1);
                    mma_bf16(s0, ql[ks][0], ql[ks][1], ql[ks][2], ql[ks][3], bh0, bh1);
                    mma_bf16(s1, qh[ks][0], qh[ks][1], qh[ks][2], qh[ks][3], bh2, bh3);
                    mma_bf16(s1, qh[ks][0], qh[ks][1], qh[ks][2], qh[ks][3], bl2, bl3);
                    mma_bf16(s1, ql[ks][0], ql[ks][1], ql[ks][2], ql[ks][3], bh2, bh3);
                }
            }

            // --- online softmax ---
            float rmax0 = -INFINITY, rmax1 = -INFINITY;
            #pragma unroll
            for (int na = 0; na < 8; na++) {
                int col = na * 8 + (lane & 3) * 2;
                float ma = ms[col], mb = ms[col + 1];
                S[na][0] = S[na][0] * scale + ma;
                S[na][1] = S[na][1] * scale + mb;
                S[na][2] = S[na][2] * scale + ma;
                S[na][3] = S[na][3] * scale + mb;
                rmax0 = fmaxf(rmax0, fmaxf(S[na][0], S[na][1]));
                rmax1 = fmaxf(rmax1, fmaxf(S[na][2], S[na][3]));
            }
            rmax0 = fmaxf(rmax0, __shfl_xor_sync(0xffffffffu, rmax0, 1));
            rmax0 = fmaxf(rmax0, __shfl_xor_sync(0xffffffffu, rmax0, 2));
            rmax1 = fmaxf(rmax1, __shfl_xor_sync(0xffffffffu, rmax1, 1));
            rmax1 = fmaxf(rmax1, __shfl_xor_sync(0xffffffffu, rmax1, 2));

            float nm0 = fmaxf(m0r, rmax0), nm1 = fmaxf(m1r, rmax1);
            float f0 = (m0r == -INFINITY) ? 0.f : __expf(m0r - nm0);
            float f1 = (m1r == -INFINITY) ? 0.f : __expf(m1r - nm1);
            float rs0 = 0.f, rs1 = 0.f;
            #pragma unroll
            for (int na = 0; na < 8; na++) {
                float p0 = __expf(S[na][0] - nm0); p0 = (S[na][0] == -INFINITY) ? 0.f : p0;
                float p1 = __expf(S[na][1] - nm0); p1 = (S[na][1] == -INFINITY) ? 0.f : p1;
                float p2 = __expf(S[na][2] - nm1); p2 = (S[na][2] == -INFINITY) ? 0.f : p2;
                float p3 = __expf(S[na][3] - nm1); p3 = (S[na][3] == -INFINITY) ? 0.f : p3;
                S[na][0] = p0; S[na][1] = p1; S[na][2] = p2; S[na][3] = p3;
                rs0 += p0 + p1; rs1 += p2 + p3;
            }
            rs0 += __shfl_xor_sync(0xffffffffu, rs0, 1);
            rs0 += __shfl_xor_sync(0xffffffffu, rs0, 2);
            rs1 += __shfl_xor_sync(0xffffffffu, rs1, 1);
            rs1 += __shfl_xor_sync(0xffffffffu, rs1, 2);
            l0r = l0r * f0 + rs0;  m0r = nm0;
            l1r = l1r * f1 + rs1;  m1r = nm1;

            #pragma unroll
            for (int na = 0; na < 8; na++) {
                O[na][0] *= f0; O[na][1] *= f0;
                O[na][2] *= f1; O[na][3] *= f1;
            }

            // --- O += P V ---
            #pragma unroll
            for (int kk = 0; kk < 4; kk++) {
                uint32_t ph[4], pl[4];
                split_pair(S[2 * kk][0],     S[2 * kk][1],     ph[0], pl[0]);
                split_pair(S[2 * kk][2],     S[2 * kk][3],     ph[1], pl[1]);
                split_pair(S[2 * kk + 1][0], S[2 * kk + 1][1], ph[2], pl[2]);
                split_pair(S[2 * kk + 1][2], S[2 * kk + 1][3], ph[3], pl[3]);
                #pragma unroll
                for (int pr = 0; pr < 4; pr++) {
                    uint32_t bh0, bh1, bh2, bh3, bl0, bl1, bl2, bl3;
                    ldsm_x4_t(smem_u32(&Vh[(kk * 16 + vrow) * KP + pr * 16 + vco]),
                              bh0, bh1, bh2, bh3);
                    ldsm_x4_t(smem_u32(&Vl[(kk * 16 + vrow) * KP + pr * 16 + vco]),
                              bl0, bl1, bl2, bl3);
                    float* o0 = O[pr * 2];
                    float* o1 = O[pr * 2 + 1];
                    mma_bf16(o0, ph[0], ph[1], ph[2], ph[3], bh0, bh1);
                    mma_bf16(o0, ph[0], ph[1], ph[2], ph[3], bl0, bl1);
                    mma_bf16(o0, pl[0], pl[1], pl[2], pl[3], bh0, bh1);
                    mma_bf16(o1, ph[0], ph[1], ph[2], ph[3], bh2, bh3);
                    mma_bf16(o1, ph[0], ph[1], ph[2], ph[3], bl2, bl3);
                    mma_bf16(o1, pl[0], pl[1], pl[2], pl[3], bh2, bh3);
                }
            }
            __syncthreads();
        }
    }

    // --- store UNNORMALIZED partials + (m,l) ---
    int row0 = q0 + warp * 16 + (lane >> 2);
    float* Op = g_Op[seg];
    #pragma unroll
    for (int na = 0; na < 8; na++) {
        int col = na * 8 + (lane & 3) * 2;
        *(float2*)&Op[((size_t)b * SS + row0) * DD + col] =
            make_float2(O[na][0], O[na][1]);
        *(float2*)&Op[((size_t)b * SS + row0 + 8) * DD + col] =
            make_float2(O[na][2], O[na][3]);
    }
    if ((lane & 3) == 0) {
        size_t r = (size_t)b * SS + row0;
        g_mp[seg][r] = m0r;     g_lp[seg][r] = l0r;
        g_mp[seg][r + 8] = m1r; g_lp[seg][r + 8] = l1r;
    }
}

// ---------------------------------------------------------------------------
// combine split-KV partials (3-way), 2 float4 per thread
// ---------------------------------------------------------------------------
__global__ void combine_kernel(float* __restrict__ out) {
    int base = blockIdx.x * 512 + threadIdx.x;
    #pragma unroll
    for (int u = 0; u < 2; u++) {
        int idx = base + u * 256;
        int row = idx >> 4;
        float m0 = g_mp[0][row], m1 = g_mp[1][row], m2 = g_mp[2][row];
        float M = fmaxf(fmaxf(m0, m1), m2);
        float w0 = (m0 == -INFINITY) ? 0.f : __expf(m0 - M);
        float w1 = (m1 == -INFINITY) ? 0.f : __expf(m1 - M);
        float w2 = (m2 == -INFINITY) ? 0.f : __expf(m2 - M);
        float inv = 1.f / (w0 * g_lp[0][row] + w1 * g_lp[1][row] + w2 * g_lp[2][row]);
        float a0 = w0 * inv, a1 = w1 * inv, a2 = w2 * inv;
        float4 o0 = reinterpret_cast<const float4*>(g_Op[0])[idx];
        float4 o1 = reinterpret_cast<const float4*>(g_Op[1])[idx];
        float4 o2 = reinterpret_cast<const float4*>(g_Op[2])[idx];
        float4 r;
        r.x = o0.x * a0 + o1.x * a1 + o2.x * a2;
        r.y = o0.y * a0 + o1.y * a1 + o2.y * a2;
        r.z = o0.z * a0 + o1.z * a1 + o2.z * a2;
        r.w = o0.w * a0 + o1.w * a1 + o2.w * a2;
        reinterpret_cast<float4*>(out)[idx] = r;
    }
}

// ---------------------------------------------------------------------------
// Launch
// ---------------------------------------------------------------------------
extern "C" void kernel_launch(void* const* d_in, const int* in_sizes, int n_in,
                              void* d_out, int out_size) {
    const float* x  = (const float*)d_in[0];
    const float* Wq = (const float*)d_in[1];
    const float* bq = (const float*)d_in[2];
    const float* Wk = (const float*)d_in[3];
    const float* bk = (const float*)d_in[4];
    const float* Wv = (const float*)d_in[5];
    const float* bv = (const float*)d_in[6];
    const int*   pm = (const int*)d_in[7];
    float* out = (float*)d_out;

    prep_w<<<3 * 64 * 512 / 256, 256>>>(Wq, Wk, Wv);
    prep_mask<<<BB, 256>>>(pm);

    cudaFuncSetAttribute(proj_kernel, cudaFuncAttributeMaxDynamicSharedMemorySize,
                         PROJ_SMEM_BYTES);
    proj_kernel<<<dim3(SS / 64, BB, 2), 256, PROJ_SMEM_BYTES>>>(x, bq, bk, bv);

    cudaFuncSetAttribute(attn_kernel, cudaFuncAttributeMaxDynamicSharedMemorySize,
                         ATTN_SMEM_BYTES);
    attn_kernel<<<dim3(SS / 64, BB, NSEG), 128, ATTN_SMEM_BYTES>>>();

    combine_kernel<<<BB * SS * DD / 8 / 256, 256>>>(out);
}

// round 12
// speedup vs baseline: 1.0047x; 1.0047x over previous
#include <cuda_runtime.h>
#include <cstdint>
#include <math.h>

#define BB 8
#define SS 2048
#define EE 1024
#define DD 64
#define NSEG 3              // split-KV segments
#define NEGBIG (-1.0e30f)   // finite -inf sentinel (absorbs, no NaN from inf-inf)

// q (all rows, scattered) and k,v (COMPACTED rows) as bf16 hi/lo planes
__device__ unsigned int g_qh[BB * SS * DD / 2];
__device__ unsigned int g_ql[BB * SS * DD / 2];
__device__ unsigned int g_kh[BB * SS * DD / 2];
__device__ unsigned int g_kl[BB * SS * DD / 2];
__device__ unsigned int g_vh[BB * SS * DD / 2];
__device__ unsigned int g_vl[BB * SS * DD / 2];

// W planes (bf16 hi/lo), [mat][n][k/2] u32
__device__ unsigned int g_Wh[3 * 64 * 512];
__device__ unsigned int g_Wl[3 * 64 * 512];

// mask compaction: unmasked list, masked list, unmasked count
__device__ int g_kidx[BB][SS];
__device__ int g_midx[BB][SS];
__device__ int g_kcnt[BB];

// split-KV partials
__device__ float g_Op[NSEG][BB * SS * DD];
__device__ float g_mp[NSEG][BB * SS];
__device__ float g_lp[NSEG][BB * SS];

// ---------------------------------------------------------------------------
// helpers
// ---------------------------------------------------------------------------
__device__ __forceinline__ uint32_t smem_u32(const void* p) {
    return (uint32_t)__cvta_generic_to_shared(p);
}

__device__ __forceinline__ void ldsm_x4(uint32_t addr, uint32_t& r0, uint32_t& r1,
                                        uint32_t& r2, uint32_t& r3) {
    asm volatile("ldmatrix.sync.aligned.m8n8.x4.shared.b16 {%0,%1,%2,%3}, [%4];"
                 : "=r"(r0), "=r"(r1), "=r"(r2), "=r"(r3) : "r"(addr));
}

__device__ __forceinline__ void ldsm_x4_t(uint32_t addr, uint32_t& r0, uint32_t& r1,
                                          uint32_t& r2, uint32_t& r3) {
    asm volatile("ldmatrix.sync.aligned.m8n8.x4.trans.shared.b16 {%0,%1,%2,%3}, [%4];"
                 : "=r"(r0), "=r"(r1), "=r"(r2), "=r"(r3) : "r"(addr));
}

__device__ __forceinline__ void mma_bf16(float c[4],
                                         uint32_t a0, uint32_t a1, uint32_t a2, uint32_t a3,
                                         uint32_t b0, uint32_t b1) {
    asm volatile("mma.sync.aligned.m16n8k16.row.col.f32.bf16.bf16.f32 "
                 "{%0,%1,%2,%3}, {%4,%5,%6,%7}, {%8,%9}, {%0,%1,%2,%3};"
                 : "+f"(c[0]), "+f"(c[1]), "+f"(c[2]), "+f"(c[3])
                 : "r"(a0), "r"(a1), "r"(a2), "r"(a3), "r"(b0), "r"(b1));
}

__device__ __forceinline__ uint32_t pack2(float x0, float x1) {
    uint32_t h;
    asm("cvt.rn.bf16x2.f32 %0, %1, %2;" : "=r"(h) : "f"(x1), "f"(x0));
    return h;
}

__device__ __forceinline__ void split_pair(float x0, float x1, uint32_t& hi, uint32_t& lo) {
    hi = pack2(x0, x1);
    float h0 = __uint_as_float(hi << 16);
    float h1 = __uint_as_float(hi & 0xffff0000u);
    lo = pack2(x0 - h0, x1 - h1);
}

__device__ __forceinline__ void cp16(uint32_t s, const void* g) {
    asm volatile("cp.async.cg.shared.global [%0], [%1], 16;" :: "r"(s), "l"(g));
}

// ---------------------------------------------------------------------------
// prep kernels
// ---------------------------------------------------------------------------
__global__ void prep_w(const float* __restrict__ Wq, const float* __restrict__ Wk,
                       const float* __restrict__ Wv) {
    int idx = blockIdx.x * 256 + threadIdx.x;
    int mat = idx >> 15;
    int off = idx & 32767;
    const float* W = (mat == 0) ? Wq : (mat == 1) ? Wk : Wv;
    float2 v = reinterpret_cast<const float2*>(W)[off];
    uint32_t h, l;
    split_pair(v.x, v.y, h, l);
    g_Wh[idx] = h;
    g_Wl[idx] = l;
}

__global__ void prep_mask(const int* __restrict__ mask) {
    const int b = blockIdx.x;
    const int t = threadIdx.x;
    __shared__ int wsum[8];
    const int* mrow = mask + (size_t)b * SS;

    int um[8], loc[8], cnt = 0;
    #pragma unroll
    for (int j = 0; j < 8; j++) {
        int s = t * 8 + j;
        um[j] = (mrow[s] == 0);
        loc[j] = cnt;
        cnt += um[j];
    }
    const int lane = t & 31, w = t >> 5;
    int inc = cnt;
    #pragma unroll
    for (int off = 1; off < 32; off <<= 1) {
        int n = __shfl_up_sync(0xffffffffu, inc, off);
        if (lane >= off) inc += n;
    }
    if (lane == 31) wsum[w] = inc;
    __syncthreads();
    int wbase = 0;
    #pragma unroll
    for (int i = 0; i < 8; i++)
        if (i < w) wbase += wsum[i];
    const int base = wbase + inc - cnt;
    #pragma unroll
    for (int j = 0; j < 8; j++) {
        int s = t * 8 + j;
        int u = base + loc[j];          // unmasked strictly before s
        if (um[j]) g_kidx[b][u] = s;
        else       g_midx[b][s - u] = s;
    }
    if (t == 255) g_kcnt[b] = base + cnt;
}

// ---------------------------------------------------------------------------
// Projection body, templated on NMAT.
//   NMAT=3: gathered UNMASKED rows -> Q (scattered to orig rows) + K,V (compact)
//   NMAT=1: gathered MASKED rows   -> Q only (scattered to orig rows)
// BM=64, BK=32, 256 threads. W planes via cp.async double-buffer; x via
// single-slab f32 register prefetch; X staged with 2 x STS.128 per thread.
// ---------------------------------------------------------------------------
#define QP 40
#define XPL (64 * QP)            // u16 per plane
#define XSTG (2 * XPL)
#define WBASE (2 * XSTG)
#define PROJ_SMEM_BYTES ((WBASE + 2 * 6 * XPL) * 2)   // sized for NMAT=3

template<int NMAT>
__device__ __forceinline__ void proj_body(
    unsigned short* qsm, const float* __restrict__ x,
    const float* __restrict__ bq, const float* __restrict__ bk,
    const float* __restrict__ bv,
    int b, int j0, int cnt, const int* __restrict__ list)
{
    constexpr int WSTGP = 2 * NMAT;

    const int t = threadIdx.x;
    const int warp = t >> 5, lane = t & 31;
    const int wm = warp >> 1;
    const int wn = warp & 1;

    float acc[NMAT][4][4] = {};

    const int arow = wm * 16 + (lane & 15);
    const int acol = (lane >> 4) * 8;
    const int brow = (lane & 7) + ((lane >> 4) << 3);
    const int bcol = ((lane >> 3) & 1) * 8;

    const int xr = t >> 2;             // staged row within tile
    const int xc = (t & 3) * 8;        // f32 col base (16B-aligned in smem)

    // gather source row (clamped tail -> duplicate rows, consistent outputs)
    int jg = j0 + xr;
    if (jg > cnt - 1) jg = cnt - 1;
    const float* xrow = x + ((size_t)b * SS + list[jg]) * EE;

    // W stage s for k-slab: 2*NMAT planes x 256 chunks of 16B (proven map)
    auto issue_w = [&](int s, int slab) {
        #pragma unroll
        for (int i = 0; i < 2 * NMAT; i++) {
            int chunk = t + i * 256;
            int p = chunk >> 8, c = chunk & 255;
            int row = c >> 2, c4 = c & 3;
            uint32_t dst = smem_u32(&qsm[WBASE + (s * WSTGP + p) * XPL + row * QP + c4 * 8]);
            const unsigned int* srcp = (p & 1) ? g_Wl : g_Wh;
            cp16(dst, srcp + ((size_t)(p >> 1) * 32768
                              + (size_t)row * 512 + slab * 16 + c4 * 4));
        }
        asm volatile("cp.async.commit_group;");
    };

    // X stage: split 8 f32 -> 4+4 u32 planes, 2 x STS.128 (was 16 x STS.32)
    auto sts_x = [&](int s, float4 a0, float4 a1) {
        unsigned short* Xh = qsm + s * XSTG;
        unsigned short* Xl = Xh + XPL;
        uint32_t h0, l0, h1, l1, h2, l2, h3, l3;
        split_pair(a0.x, a0.y, h0, l0);
        split_pair(a0.z, a0.w, h1, l1);
        split_pair(a1.x, a1.y, h2, l2);
        split_pair(a1.z, a1.w, h3, l3);
        *reinterpret_cast<uint4*>(&Xh[xr * QP + xc]) = make_uint4(h0, h1, h2, h3);
        *reinterpret_cast<uint4*>(&Xl[xr * QP + xc]) = make_uint4(l0, l1, l2, l3);
    };

    issue_w(0, 0);
    {
        float4 a0 = *reinterpret_cast<const float4*>(&xrow[xc]);
        float4 a1 = *reinterpret_cast<const float4*>(&xrow[xc + 4]);
        sts_x(0, a0, a1);
    }
    float4 xa0 = *reinterpret_cast<const float4*>(&xrow[32 + xc]);
    float4 xa1 = *reinterpret_cast<const float4*>(&xrow[32 + xc + 4]);

    const int NI = EE / 32;
    for (int i = 0; i < NI; i++) {
        const int s = i & 1;

        asm volatile("cp.async.wait_group 0;");
        __syncthreads();

        if (i + 1 < NI) {
            issue_w(s ^ 1, i + 1);
            sts_x(s ^ 1, xa0, xa1);
            if (i + 2 < NI) {
                int kn = (i + 2) * 32;
                xa0 = *reinterpret_cast<const float4*>(&xrow[kn + xc]);
                xa1 = *reinterpret_cast<const float4*>(&xrow[kn + xc + 4]);
            }
        }

        const unsigned short* Xh = qsm + s * XSTG;
        const unsigned short* Xl = Xh + XPL;
        const unsigned short* Wb = qsm + WBASE + s * WSTGP * XPL;

        #pragma unroll
        for (int ks = 0; ks < 2; ks++) {
            uint32_t ah[4], al[4];
            ldsm_x4(smem_u32(&Xh[arow * QP + ks * 16 + acol]), ah[0], ah[1], ah[2], ah[3]);
            ldsm_x4(smem_u32(&Xl[arow * QP + ks * 16 + acol]), al[0], al[1], al[2], al[3]);
            #pragma unroll
            for (int mm = 0; mm < NMAT; mm++) {
                const unsigned short* Wh = Wb + (mm * 2) * XPL;
                const unsigned short* Wl = Wh + XPL;
                #pragma unroll
                for (int pr = 0; pr < 2; pr++) {
                    uint32_t bh0, bh1, bh2, bh3, bl0, bl1, bl2, bl3;
                    ldsm_x4(smem_u32(&Wh[(wn * 32 + pr * 16 + brow) * QP + ks * 16 + bcol]),
                            bh0, bh1, bh2, bh3);
                    ldsm_x4(smem_u32(&Wl[(wn * 32 + pr * 16 + brow) * QP + ks * 16 + bcol]),
                            bl0, bl1, bl2, bl3);
                    float* c0 = acc[mm][pr * 2];
                    float* c1 = acc[mm][pr * 2 + 1];
                    mma_bf16(c0, ah[0], ah[1], ah[2], ah[3], bh0, bh1);
                    mma_bf16(c0, ah[0], ah[1], ah[2], ah[3], bl0, bl1);
                    mma_bf16(c0, al[0], al[1], al[2], al[3], bh0, bh1);
                    mma_bf16(c1, ah[0], ah[1], ah[2], ah[3], bh2, bh3);
                    mma_bf16(c1, ah[0], ah[1], ah[2], ah[3], bl2, bl3);
                    mma_bf16(c1, al[0], al[1], al[2], al[3], bh2, bh3);
                }
            }
        }
    }

    // epilogue: Q (mm=0) scattered to original rows; K/V (mm=1,2) compacted
    int jr0 = j0 + wm * 16 + (lane >> 2);
    int jr8 = jr0 + 8;
    if (jr0 > cnt - 1) jr0 = cnt - 1;
    if (jr8 > cnt - 1) jr8 = cnt - 1;
    const size_t qrow0 = (size_t)b * SS + list[jr0];
    const size_t qrow8 = (size_t)b * SS + list[jr8];

    #pragma unroll
    for (int mm = 0; mm < NMAT; mm++) {
        const float* bias = (mm == 0) ? bq : (mm == 1) ? bk : bv;
        unsigned int* gh = (mm == 0) ? g_qh : (mm == 1) ? g_kh : g_vh;
        unsigned int* gl = (mm == 0) ? g_ql : (mm == 1) ? g_kl : g_vl;
        size_t r0, r8;
        if (mm == 0) { r0 = qrow0; r8 = qrow8; }
        else {
            r0 = (size_t)b * SS + j0 + wm * 16 + (lane >> 2);
            r8 = r0 + 8;
        }
        #pragma unroll
        for (int na = 0; na < 4; na++) {
            int col = wn * 32 + na * 8 + (lane & 3) * 2;
            float b0 = bias[col], b1 = bias[col + 1];
            float c0 = acc[mm][na][0] + b0, c1 = acc[mm][na][1] + b1;
            float c2 = acc[mm][na][2] + b0, c3 = acc[mm][na][3] + b1;
            uint32_t h, l;
            split_pair(c0, c1, h, l);
            gh[r0 * 32 + col / 2] = h;
            gl[r0 * 32 + col / 2] = l;
            split_pair(c2, c3, h, l);
            gh[r8 * 32 + col / 2] = h;
            gl[r8 * 32 + col / 2] = l;
        }
    }
}

__global__ __launch_bounds__(256, 2) void proj_kernel(
    const float* __restrict__ x,
    const float* __restrict__ bq, const float* __restrict__ bk,
    const float* __restrict__ bv)
{
    extern __shared__ unsigned short qsm[];
    const int b = blockIdx.y;
    const int j0 = blockIdx.x * 64;
    const int nk = g_kcnt[b];

    if (blockIdx.z == 0) {
        if (j0 >= nk) return;
        proj_body<3>(qsm, x, bq, bk, bv, b, j0, nk, g_kidx[b]);
    } else {
        const int nm = SS - nk;
        if (j0 >= nm || nm == 0) return;
        proj_body<1>(qsm, x, bq, bk, bv, b, j0, nm, g_midx[b]);
    }
}

// ---------------------------------------------------------------------------
// Flash attention over COMPACTED keys, split-KV x3. Finite -1e30 sentinel:
// no inf guards needed anywhere (every in-range tile has >=1 real key, so
// nm is real whenever masked entries coexist; exp(-1e30 - real) == 0).
// ---------------------------------------------------------------------------
#define KP 72
#define TILE_U16 (64 * KP)
#define STAGE_U16 (4 * TILE_U16)
#define ATTN_SMEM_BYTES (2 * STAGE_U16 * 2 + 64 * 4)

__device__ __forceinline__ void stage_tile(uint32_t sbase, size_t gbase, int t) {
    #pragma unroll
    for (int i = 0; i < 4; i++) {
        int chunk = t + i * 128;
        int r = chunk >> 3, c = chunk & 7;
        uint32_t soff = (uint32_t)(r * KP + c * 8) * 2;
        size_t goff = (size_t)r * 32 + c * 4;
        cp16(sbase + soff,                     g_kh + gbase + goff);
        cp16(sbase + TILE_U16 * 2 + soff,      g_kl + gbase + goff);
        cp16(sbase + 2 * TILE_U16 * 2 + soff,  g_vh + gbase + goff);
        cp16(sbase + 3 * TILE_U16 * 2 + soff,  g_vl + gbase + goff);
    }
    asm volatile("cp.async.commit_group;");
}

__global__ __launch_bounds__(128, 3) void attn_kernel()
{
    extern __shared__ unsigned short sm[];
    float* ms = (float*)(sm + 2 * STAGE_U16);

    const int t = threadIdx.x, warp = t >> 5, lane = t & 31;
    const int b = blockIdx.y, q0 = blockIdx.x * 64;
    const int seg = blockIdx.z;

    const int nk = g_kcnt[b];
    const int T = (nk + 63) >> 6;
    const int bnt = T / 3, rem = T - bnt * 3;
    const int nt = bnt + (seg < rem ? 1 : 0);
    const int t0 = seg * bnt + (seg < rem ? seg : rem);

    // --- stage Q into stage-0, extract fragments ---
    {
        uint32_t s0 = smem_u32(sm);
        size_t gq = ((size_t)b * SS + q0) * 32;
        #pragma unroll
        for (int i = 0; i < 4; i++) {
            int chunk = t + i * 128;
            int r = chunk >> 3, c = chunk & 7;
            uint32_t soff = (uint32_t)(r * KP + c * 8) * 2;
            size_t goff = (size_t)r * 32 + c * 4;
            cp16(s0 + soff,                g_qh + gq + goff);
            cp16(s0 + TILE_U16 * 2 + soff, g_ql + gq + goff);
        }
        asm volatile("cp.async.commit_group;");
        asm volatile("cp.async.wait_group 0;");
        __syncthreads();
    }

    uint32_t qh[4][4], ql[4][4];
    {
        const int arow = warp * 16 + (lane & 15);
        const int acol = (lane >> 4) * 8;
        #pragma unroll
        for (int ks = 0; ks < 4; ks++) {
            ldsm_x4(smem_u32(&sm[arow * KP + ks * 16 + acol]),
                    qh[ks][0], qh[ks][1], qh[ks][2], qh[ks][3]);
            ldsm_x4(smem_u32(&sm[TILE_U16 + arow * KP + ks * 16 + acol]),
                    ql[ks][0], ql[ks][1], ql[ks][2], ql[ks][3]);
        }
    }
    __syncthreads();

    float O[8][4] = {};
    float m0r = NEGBIG, m1r = NEGBIG, l0r = 0.f, l1r = 0.f;
    const float scale = 0.125f;

    const uint32_t stage_addr[2] = { smem_u32(sm), smem_u32(sm + STAGE_U16) };

    if (nt > 0) {
        stage_tile(stage_addr[0], ((size_t)b * SS + t0 * 64) * 32, t);

        const int brow = (lane & 7) + ((lane >> 4) << 3);
        const int bco  = ((lane >> 3) & 1) * 8;
        const int vrow = lane & 15;
        const int vco  = (lane >> 4) * 8;

        for (int it = 0; it < nt; ++it) {
            const int st = it & 1;
            const unsigned short* Kh = sm + st * STAGE_U16;
            const unsigned short* Kl = Kh + TILE_U16;
            const unsigned short* Vh = Kh + 2 * TILE_U16;
            const unsigned short* Vl = Kh + 3 * TILE_U16;

            if (it + 1 < nt)
                stage_tile(stage_addr[st ^ 1], ((size_t)b * SS + (t0 + it + 1) * 64) * 32, t);
            if (t < 64) ms[t] = ((t0 + it) * 64 + t < nk) ? 0.f : NEGBIG;

            if (it + 1 < nt) asm volatile("cp.async.wait_group 1;");
            else             asm volatile("cp.async.wait_group 0;");
            __syncthreads();

            // --- S = Q K^T ---
            float S[8][4] = {};
            #pragma unroll
            for (int ks = 0; ks < 4; ks++) {
                #pragma unroll
                for (int pr = 0; pr < 4; pr++) {
                    uint32_t bh0, bh1, bh2, bh3, bl0, bl1, bl2, bl3;
                    ldsm_x4(smem_u32(&Kh[(pr * 16 + brow) * KP + ks * 16 + bco]),
                            bh0, bh1, bh2, bh3);
                    ldsm_x4(smem_u32(&Kl[(pr * 16 + brow) * KP + ks * 16 + bco]),
                            bl0, bl1, bl2, bl3);
                    float* s0 = S[pr * 2];
                    float* s1 = S[pr * 2 + 1];
                    mma_bf16(s0, qh[ks][0], qh[ks][1], qh[ks][2], qh[ks][3], bh0, bh1);
                    mma_bf16(s0, qh[ks][0], qh[ks][1], qh[ks][2], qh[ks][3], bl0, bl1);
                    mma_bf16(s0, ql[ks][0], ql[ks][1], ql[ks][2], ql[ks][3], bh0, bh1);
                    mma_bf16(s1, qh[ks][0], qh[ks][1], qh[ks][2], qh[ks][3], bh2, bh3);
                    mma_bf16(s1, qh[ks][0], qh[ks][1], qh[ks][2], qh[ks][3], bl2, bl3);
                    mma_bf16(s1, ql[ks][0], ql[ks][1], ql[ks][2], ql[ks][3], bh2, bh3);
                }
            }

            // --- online softmax (finite sentinel; no inf guards) ---
            float rmax0 = NEGBIG, rmax1 = NEGBIG;
            #pragma unroll
            for (int na = 0; na < 8; na++) {
                int col = na * 8 + (lane & 3) * 2;
                float ma = ms[col], mb = ms[col + 1];
                S[na][0] = S[na][0] * scale + ma;
                S[na][1] = S[na][1] * scale + mb;
                S[na][2] = S[na][2] * scale + ma;
                S[na][3] = S[na][3] * scale + mb;
                rmax0 = fmaxf(rmax0, fmaxf(S[na][0], S[na][1]));
                rmax1 = fmaxf(rmax1, fmaxf(S[na][2], S[na][3]));
            }
            rmax0 = fmaxf(rmax0, __shfl_xor_sync(0xffffffffu, rmax0, 1));
            rmax0 = fmaxf(rmax0, __shfl_xor_sync(0xffffffffu, rmax0, 2));
            rmax1 = fmaxf(rmax1, __shfl_xor_sync(0xffffffffu, rmax1, 1));
            rmax1 = fmaxf(rmax1, __shfl_xor_sync(0xffffffffu, rmax1, 2));

            float nm0 = fmaxf(m0r, rmax0), nm1 = fmaxf(m1r, rmax1);
            float f0 = __expf(m0r - nm0);
            float f1 = __expf(m1r - nm1);
            float rs0 = 0.f, rs1 = 0.f;
            #pragma unroll
            for (int na = 0; na < 8; na++) {
                float p0 = __expf(S[na][0] - nm0);
                float p1 = __expf(S[na][1] - nm0);
                float p2 = __expf(S[na][2] - nm1);
                float p3 = __expf(S[na][3] - nm1);
                S[na][0] = p0; S[na][1] = p1; S[na][2] = p2; S[na][3] = p3;
                rs0 += p0 + p1; rs1 += p2 + p3;
            }
            rs0 += __shfl_xor_sync(0xffffffffu, rs0, 1);
            rs0 += __shfl_xor_sync(0xffffffffu, rs0, 2);
            rs1 += __shfl_xor_sync(0xffffffffu, rs1, 1);
            rs1 += __shfl_xor_sync(0xffffffffu, rs1, 2);
            l0r = l0r * f0 + rs0;  m0r = nm0;
            l1r = l1r * f1 + rs1;  m1r = nm1;

            #pragma unroll
            for (int na = 0; na < 8; na++) {
                O[na][0] *= f0; O[na][1] *= f0;
                O[na][2] *= f1; O[na][3] *= f1;
            }

            // --- O += P V ---
            #pragma unroll
            for (int kk = 0; kk < 4; kk++) {
                uint32_t ph[4], pl[4];
                split_pair(S[2 * kk][0],     S[2 * kk][1],     ph[0], pl[0]);
                split_pair(S[2 * kk][2],     S[2 * kk][3],     ph[1], pl[1]);
                split_pair(S[2 * kk + 1][0], S[2 * kk + 1][1], ph[2], pl[2]);
                split_pair(S[2 * kk + 1][2], S[2 * kk + 1][3], ph[3], pl[3]);
                #pragma unroll
                for (int pr = 0; pr < 4; pr++) {
                    uint32_t bh0, bh1, bh2, bh3, bl0, bl1, bl2, bl3;
                    ldsm_x4_t(smem_u32(&Vh[(kk * 16 + vrow) * KP + pr * 16 + vco]),
                              bh0, bh1, bh2, bh3);
                    ldsm_x4_t(smem_u32(&Vl[(kk * 16 + vrow) * KP + pr * 16 + vco]),
                              bl0, bl1, bl2, bl3);
                    float* o0 = O[pr * 2];
                    float* o1 = O[pr * 2 + 1];
                    mma_bf16(o0, ph[0], ph[1], ph[2], ph[3], bh0, bh1);
                    mma_bf16(o0, ph[0], ph[1], ph[2], ph[3], bl0, bl1);
                    mma_bf16(o0, pl[0], pl[1], pl[2], pl[3], bh0, bh1);
                    mma_bf16(o1, ph[0], ph[1], ph[2], ph[3], bh2, bh3);
                    mma_bf16(o1, ph[0], ph[1], ph[2], ph[3], bl2, bl3);
                    mma_bf16(o1, pl[0], pl[1], pl[2], pl[3], bh2, bh3);
                }
            }
            __syncthreads();
        }
    }

    // --- store UNNORMALIZED partials + (m,l) ---
    int row0 = q0 + warp * 16 + (lane >> 2);
    float* Op = g_Op[seg];
    #pragma unroll
    for (int na = 0; na < 8; na++) {
        int col = na * 8 + (lane & 3) * 2;
        *(float2*)&Op[((size_t)b * SS + row0) * DD + col] =
            make_float2(O[na][0], O[na][1]);
        *(float2*)&Op[((size_t)b * SS + row0 + 8) * DD + col] =
            make_float2(O[na][2], O[na][3]);
    }
    if ((lane & 3) == 0) {
        size_t r = (size_t)b * SS + row0;
        g_mp[seg][r] = m0r;     g_lp[seg][r] = l0r;
        g_mp[seg][r + 8] = m1r; g_lp[seg][r + 8] = l1r;
    }
}

// ---------------------------------------------------------------------------
// combine split-KV partials (3-way), 2 float4 per thread, finite sentinel
// ---------------------------------------------------------------------------
__global__ void combine_kernel(float* __restrict__ out) {
    int base = blockIdx.x * 512 + threadIdx.x;
    #pragma unroll
    for (int u = 0; u < 2; u++) {
        int idx = base + u * 256;
        int row = idx >> 4;
        float m0 = g_mp[0][row], m1 = g_mp[1][row], m2 = g_mp[2][row];
        float M = fmaxf(fmaxf(m0, m1), m2);
        float w0 = __expf(m0 - M);
        float w1 = __expf(m1 - M);
        float w2 = __expf(m2 - M);
        float inv = 1.f / (w0 * g_lp[0][row] + w1 * g_lp[1][row] + w2 * g_lp[2][row]);
        float a0 = w0 * inv, a1 = w1 * inv, a2 = w2 * inv;
        float4 o0 = reinterpret_cast<const float4*>(g_Op[0])[idx];
        float4 o1 = reinterpret_cast<const float4*>(g_Op[1])[idx];
        float4 o2 = reinterpret_cast<const float4*>(g_Op[2])[idx];
        float4 r;
        r.x = o0.x * a0 + o1.x * a1 + o2.x * a2;
        r.y = o0.y * a0 + o1.y * a1 + o2.y * a2;
        r.z = o0.z * a0 + o1.z * a1 + o2.z * a2;
        r.w = o0.w * a0 + o1.w * a1 + o2.w * a2;
        reinterpret_cast<float4*>(out)[idx] = r;
    }
}

// ---------------------------------------------------------------------------
// Launch
// ---------------------------------------------------------------------------
extern "C" void kernel_launch(void* const* d_in, const int* in_sizes, int n_in,
                              void* d_out, int out_size) {
    const float* x  = (const float*)d_in[0];
    const float* Wq = (const float*)d_in[1];
    const float* bq = (const float*)d_in[2];
    const float* Wk = (const float*)d_in[3];
    const float* bk = (const float*)d_in[4];
    const float* Wv = (const float*)d_in[5];
    const float* bv = (const float*)d_in[6];
    const int*   pm = (const int*)d_in[7];
    float* out = (float*)d_out;

    prep_w<<<3 * 64 * 512 / 256, 256>>>(Wq, Wk, Wv);
    prep_mask<<<BB, 256>>>(pm);

    cudaFuncSetAttribute(proj_kernel, cudaFuncAttributeMaxDynamicSharedMemorySize,
                         PROJ_SMEM_BYTES);
    proj_kernel<<<dim3(SS / 64, BB, 2), 256, PROJ_SMEM_BYTES>>>(x, bq, bk, bv);

    cudaFuncSetAttribute(attn_kernel, cudaFuncAttributeMaxDynamicSharedMemorySize,
                         ATTN_SMEM_BYTES);
    attn_kernel<<<dim3(SS / 64, BB, NSEG), 128, ATTN_SMEM_BYTES>>>();

    combine_kernel<<<BB * SS * DD / 8 / 256, 256>>>(out);
}

// round 14
// speedup vs baseline: 1.0178x; 1.0131x over previous
#include <cuda_runtime.h>
#include <cstdint>
#include <math.h>

#define BB 8
#define SS 2048
#define EE 1024
#define DD 64
#define NSLOT 4             // split-KV partial slots (persistent scheduler)
#define NCTA 444            // persistent attn grid = 148 SMs x 3 CTAs
#define NEGBIG (-1.0e30f)   // finite -inf sentinel
#define WBLK 384            // prep: W-split blocks (3*64*512/256)

// q (all rows, scattered) and k,v (COMPACTED rows) as bf16 hi/lo planes
__device__ unsigned int g_qh[BB * SS * DD / 2];
__device__ unsigned int g_ql[BB * SS * DD / 2];
__device__ unsigned int g_kh[BB * SS * DD / 2];
__device__ unsigned int g_kl[BB * SS * DD / 2];
__device__ unsigned int g_vh[BB * SS * DD / 2];
__device__ unsigned int g_vl[BB * SS * DD / 2];

// W planes (bf16 hi/lo), [mat][n][k/2] u32
__device__ unsigned int g_Wh[3 * 64 * 512];
__device__ unsigned int g_Wl[3 * 64 * 512];

// mask compaction
__device__ int g_kidx[BB][SS];
__device__ int g_midx[BB][SS];
__device__ int g_kcnt[BB];

// split-KV partials (zero-init; unused slots contribute exactly 0 in combine)
__device__ float g_Op[NSLOT][BB * SS * DD];
__device__ float g_mp[NSLOT][BB * SS];
__device__ float g_lp[NSLOT][BB * SS];

// ---------------------------------------------------------------------------
// helpers
// ---------------------------------------------------------------------------
__device__ __forceinline__ uint32_t smem_u32(const void* p) {
    return (uint32_t)__cvta_generic_to_shared(p);
}

__device__ __forceinline__ void ldsm_x4(uint32_t addr, uint32_t& r0, uint32_t& r1,
                                        uint32_t& r2, uint32_t& r3) {
    asm volatile("ldmatrix.sync.aligned.m8n8.x4.shared.b16 {%0,%1,%2,%3}, [%4];"
                 : "=r"(r0), "=r"(r1), "=r"(r2), "=r"(r3) : "r"(addr));
}

__device__ __forceinline__ void ldsm_x4_t(uint32_t addr, uint32_t& r0, uint32_t& r1,
                                          uint32_t& r2, uint32_t& r3) {
    asm volatile("ldmatrix.sync.aligned.m8n8.x4.trans.shared.b16 {%0,%1,%2,%3}, [%4];"
                 : "=r"(r0), "=r"(r1), "=r"(r2), "=r"(r3) : "r"(addr));
}

__device__ __forceinline__ void mma_bf16(float c[4],
                                         uint32_t a0, uint32_t a1, uint32_t a2, uint32_t a3,
                                         uint32_t b0, uint32_t b1) {
    asm volatile("mma.sync.aligned.m16n8k16.row.col.f32.bf16.bf16.f32 "
                 "{%0,%1,%2,%3}, {%4,%5,%6,%7}, {%8,%9}, {%0,%1,%2,%3};"
                 : "+f"(c[0]), "+f"(c[1]), "+f"(c[2]), "+f"(c[3])
                 : "r"(a0), "r"(a1), "r"(a2), "r"(a3), "r"(b0), "r"(b1));
}

__device__ __forceinline__ uint32_t pack2(float x0, float x1) {
    uint32_t h;
    asm("cvt.rn.bf16x2.f32 %0, %1, %2;" : "=r"(h) : "f"(x1), "f"(x0));
    return h;
}

__device__ __forceinline__ void split_pair(float x0, float x1, uint32_t& hi, uint32_t& lo) {
    hi = pack2(x0, x1);
    float h0 = __uint_as_float(hi << 16);
    float h1 = __uint_as_float(hi & 0xffff0000u);
    lo = pack2(x0 - h0, x1 - h1);
}

__device__ __forceinline__ void cp16(uint32_t s, const void* g) {
    asm volatile("cp.async.cg.shared.global [%0], [%1], 16;" :: "r"(s), "l"(g));
}

// ---------------------------------------------------------------------------
// fused prep: blocks < WBLK split W; blocks >= WBLK build per-batch compaction
// ---------------------------------------------------------------------------
__global__ void prep_kernel(const float* __restrict__ Wq, const float* __restrict__ Wk,
                            const float* __restrict__ Wv, const int* __restrict__ mask) {
    if (blockIdx.x < WBLK) {
        int idx = blockIdx.x * 256 + threadIdx.x;   // < 98304 = 3*64*512
        int mat = idx >> 15;
        int off = idx & 32767;
        const float* W = (mat == 0) ? Wq : (mat == 1) ? Wk : Wv;
        float2 v = reinterpret_cast<const float2*>(W)[off];
        uint32_t h, l;
        split_pair(v.x, v.y, h, l);
        g_Wh[idx] = h;
        g_Wl[idx] = l;
        return;
    }
    const int b = blockIdx.x - WBLK;
    const int t = threadIdx.x;
    __shared__ int wsum[8];
    const int* mrow = mask + (size_t)b * SS;

    int um[8], loc[8], cnt = 0;
    #pragma unroll
    for (int j = 0; j < 8; j++) {
        int s = t * 8 + j;
        um[j] = (mrow[s] == 0);
        loc[j] = cnt;
        cnt += um[j];
    }
    const int lane = t & 31, w = t >> 5;
    int inc = cnt;
    #pragma unroll
    for (int off = 1; off < 32; off <<= 1) {
        int n = __shfl_up_sync(0xffffffffu, inc, off);
        if (lane >= off) inc += n;
    }
    if (lane == 31) wsum[w] = inc;
    __syncthreads();
    int wbase = 0;
    #pragma unroll
    for (int i = 0; i < 8; i++)
        if (i < w) wbase += wsum[i];
    const int base = wbase + inc - cnt;
    #pragma unroll
    for (int j = 0; j < 8; j++) {
        int s = t * 8 + j;
        int u = base + loc[j];
        if (um[j]) g_kidx[b][u] = s;
        else       g_midx[b][s - u] = s;
    }
    if (t == 255) g_kcnt[b] = base + cnt;
}

// ---------------------------------------------------------------------------
// Projection (unchanged from R12 champion structure)
// ---------------------------------------------------------------------------
#define QP 40
#define XPL (64 * QP)
#define XSTG (2 * XPL)
#define WBASE (2 * XSTG)
#define PROJ_SMEM_BYTES ((WBASE + 2 * 6 * XPL) * 2)

template<int NMAT>
__device__ __forceinline__ void proj_body(
    unsigned short* qsm, const float* __restrict__ x,
    const float* __restrict__ bq, const float* __restrict__ bk,
    const float* __restrict__ bv,
    int b, int j0, int cnt, const int* __restrict__ list)
{
    constexpr int WSTGP = 2 * NMAT;

    const int t = threadIdx.x;
    const int warp = t >> 5, lane = t & 31;
    const int wm = warp >> 1;
    const int wn = warp & 1;

    float acc[NMAT][4][4] = {};

    const int arow = wm * 16 + (lane & 15);
    const int acol = (lane >> 4) * 8;
    const int brow = (lane & 7) + ((lane >> 4) << 3);
    const int bcol = ((lane >> 3) & 1) * 8;

    const int xr = t >> 2;
    const int xc = (t & 3) * 8;

    int jg = j0 + xr;
    if (jg > cnt - 1) jg = cnt - 1;
    const float* xrow = x + ((size_t)b * SS + list[jg]) * EE;

    auto issue_w = [&](int s, int slab) {
        #pragma unroll
        for (int i = 0; i < 2 * NMAT; i++) {
            int chunk = t + i * 256;
            int p = chunk >> 8, c = chunk & 255;
            int row = c >> 2, c4 = c & 3;
            uint32_t dst = smem_u32(&qsm[WBASE + (s * WSTGP + p) * XPL + row * QP + c4 * 8]);
            const unsigned int* srcp = (p & 1) ? g_Wl : g_Wh;
            cp16(dst, srcp + ((size_t)(p >> 1) * 32768
                              + (size_t)row * 512 + slab * 16 + c4 * 4));
        }
        asm volatile("cp.async.commit_group;");
    };

    auto sts_x = [&](int s, float4 a0, float4 a1) {
        unsigned short* Xh = qsm + s * XSTG;
        unsigned short* Xl = Xh + XPL;
        uint32_t h0, l0, h1, l1, h2, l2, h3, l3;
        split_pair(a0.x, a0.y, h0, l0);
        split_pair(a0.z, a0.w, h1, l1);
        split_pair(a1.x, a1.y, h2, l2);
        split_pair(a1.z, a1.w, h3, l3);
        *reinterpret_cast<uint4*>(&Xh[xr * QP + xc]) = make_uint4(h0, h1, h2, h3);
        *reinterpret_cast<uint4*>(&Xl[xr * QP + xc]) = make_uint4(l0, l1, l2, l3);
    };

    issue_w(0, 0);
    {
        float4 a0 = *reinterpret_cast<const float4*>(&xrow[xc]);
        float4 a1 = *reinterpret_cast<const float4*>(&xrow[xc + 4]);
        sts_x(0, a0, a1);
    }
    float4 xa0 = *reinterpret_cast<const float4*>(&xrow[32 + xc]);
    float4 xa1 = *reinterpret_cast<const float4*>(&xrow[32 + xc + 4]);

    const int NI = EE / 32;
    for (int i = 0; i < NI; i++) {
        const int s = i & 1;

        asm volatile("cp.async.wait_group 0;");
        __syncthreads();

        if (i + 1 < NI) {
            issue_w(s ^ 1, i + 1);
            sts_x(s ^ 1, xa0, xa1);
            if (i + 2 < NI) {
                int kn = (i + 2) * 32;
                xa0 = *reinterpret_cast<const float4*>(&xrow[kn + xc]);
                xa1 = *reinterpret_cast<const float4*>(&xrow[kn + xc + 4]);
            }
        }

        const unsigned short* Xh = qsm + s * XSTG;
        const unsigned short* Xl = Xh + XPL;
        const unsigned short* Wb = qsm + WBASE + s * WSTGP * XPL;

        #pragma unroll
        for (int ks = 0; ks < 2; ks++) {
            uint32_t ah[4], al[4];
            ldsm_x4(smem_u32(&Xh[arow * QP + ks * 16 + acol]), ah[0], ah[1], ah[2], ah[3]);
            ldsm_x4(smem_u32(&Xl[arow * QP + ks * 16 + acol]), al[0], al[1], al[2], al[3]);
            #pragma unroll
            for (int mm = 0; mm < NMAT; mm++) {
                const unsigned short* Wh = Wb + (mm * 2) * XPL;
                const unsigned short* Wl = Wh + XPL;
                #pragma unroll
                for (int pr = 0; pr < 2; pr++) {
                    uint32_t bh0, bh1, bh2, bh3, bl0, bl1, bl2, bl3;
                    ldsm_x4(smem_u32(&Wh[(wn * 32 + pr * 16 + brow) * QP + ks * 16 + bcol]),
                            bh0, bh1, bh2, bh3);
                    ldsm_x4(smem_u32(&Wl[(wn * 32 + pr * 16 + brow) * QP + ks * 16 + bcol]),
                            bl0, bl1, bl2, bl3);
                    float* c0 = acc[mm][pr * 2];
                    float* c1 = acc[mm][pr * 2 + 1];
                    mma_bf16(c0, ah[0], ah[1], ah[2], ah[3], bh0, bh1);
                    mma_bf16(c0, ah[0], ah[1], ah[2], ah[3], bl0, bl1);
                    mma_bf16(c0, al[0], al[1], al[2], al[3], bh0, bh1);
                    mma_bf16(c1, ah[0], ah[1], ah[2], ah[3], bh2, bh3);
                    mma_bf16(c1, ah[0], ah[1], ah[2], ah[3], bl2, bl3);
                    mma_bf16(c1, al[0], al[1], al[2], al[3], bh2, bh3);
                }
            }
        }
    }

    int jr0 = j0 + wm * 16 + (lane >> 2);
    int jr8 = jr0 + 8;
    if (jr0 > cnt - 1) jr0 = cnt - 1;
    if (jr8 > cnt - 1) jr8 = cnt - 1;
    const size_t qrow0 = (size_t)b * SS + list[jr0];
    const size_t qrow8 = (size_t)b * SS + list[jr8];

    #pragma unroll
    for (int mm = 0; mm < NMAT; mm++) {
        const float* bias = (mm == 0) ? bq : (mm == 1) ? bk : bv;
        unsigned int* gh = (mm == 0) ? g_qh : (mm == 1) ? g_kh : g_vh;
        unsigned int* gl = (mm == 0) ? g_ql : (mm == 1) ? g_kl : g_vl;
        size_t r0, r8;
        if (mm == 0) { r0 = qrow0; r8 = qrow8; }
        else {
            r0 = (size_t)b * SS + j0 + wm * 16 + (lane >> 2);
            r8 = r0 + 8;
        }
        #pragma unroll
        for (int na = 0; na < 4; na++) {
            int col = wn * 32 + na * 8 + (lane & 3) * 2;
            float b0 = bias[col], b1 = bias[col + 1];
            float c0 = acc[mm][na][0] + b0, c1 = acc[mm][na][1] + b1;
            float c2 = acc[mm][na][2] + b0, c3 = acc[mm][na][3] + b1;
            uint32_t h, l;
            split_pair(c0, c1, h, l);
            gh[r0 * 32 + col / 2] = h;
            gl[r0 * 32 + col / 2] = l;
            split_pair(c2, c3, h, l);
            gh[r8 * 32 + col / 2] = h;
            gl[r8 * 32 + col / 2] = l;
        }
    }
}

__global__ __launch_bounds__(256, 2) void proj_kernel(
    const float* __restrict__ x,
    const float* __restrict__ bq, const float* __restrict__ bk,
    const float* __restrict__ bv)
{
    extern __shared__ unsigned short qsm[];
    const int b = blockIdx.y;
    const int j0 = blockIdx.x * 64;
    const int nk = g_kcnt[b];

    if (blockIdx.z == 0) {
        if (j0 >= nk) return;
        proj_body<3>(qsm, x, bq, bk, bv, b, j0, nk, g_kidx[b]);
    } else {
        const int nm = SS - nk;
        if (j0 >= nm || nm == 0) return;
        proj_body<1>(qsm, x, bq, bk, bv, b, j0, nm, g_midx[b]);
    }
}

// ---------------------------------------------------------------------------
// Flash attention, PERSISTENT scheduler. Grid = 444 CTAs (one full wave).
// Global tile space = all (batch, q-tile) pairs' key tiles; each CTA takes a
// contiguous chunk of W = ceil(total/444) tiles, spanning <= NSLOT pairs.
// Partial slot = CTA index - first CTA of the pair. Unused slots zero.
// ---------------------------------------------------------------------------
#define KP 72
#define TILE_U16 (64 * KP)
#define STAGE_U16 (4 * TILE_U16)
#define ATTN_SMEM_BYTES (2 * STAGE_U16 * 2 + 64 * 4)

__device__ __forceinline__ void stage_tile(uint32_t sbase, size_t gbase, int t) {
    #pragma unroll
    for (int i = 0; i < 4; i++) {
        int chunk = t + i * 128;
        int r = chunk >> 3, c = chunk & 7;
        uint32_t soff = (uint32_t)(r * KP + c * 8) * 2;
        size_t goff = (size_t)r * 32 + c * 4;
        cp16(sbase + soff,                     g_kh + gbase + goff);
        cp16(sbase + TILE_U16 * 2 + soff,      g_kl + gbase + goff);
        cp16(sbase + 2 * TILE_U16 * 2 + soff,  g_vh + gbase + goff);
        cp16(sbase + 3 * TILE_U16 * 2 + soff,  g_vl + gbase + goff);
    }
    asm volatile("cp.async.commit_group;");
}

// one pair-segment of flash attention: tiles [t0, t0+nt) of pair (b, q0)
__device__ __forceinline__ void flash_segment(
    unsigned short* sm, float* ms, int b, int q0, int t0, int nt, int nk, int slot)
{
    const int t = threadIdx.x, warp = t >> 5, lane = t & 31;

    __syncthreads();   // prior segment's smem readers done before Q restage

    // --- stage Q into stage-0, extract fragments ---
    {
        uint32_t s0 = smem_u32(sm);
        size_t gq = ((size_t)b * SS + q0) * 32;
        #pragma unroll
        for (int i = 0; i < 4; i++) {
            int chunk = t + i * 128;
            int r = chunk >> 3, c = chunk & 7;
            uint32_t soff = (uint32_t)(r * KP + c * 8) * 2;
            size_t goff = (size_t)r * 32 + c * 4;
            cp16(s0 + soff,                g_qh + gq + goff);
            cp16(s0 + TILE_U16 * 2 + soff, g_ql + gq + goff);
        }
        asm volatile("cp.async.commit_group;");
        asm volatile("cp.async.wait_group 0;");
        __syncthreads();
    }

    uint32_t qh[4][4], ql[4][4];
    {
        const int arow = warp * 16 + (lane & 15);
        const int acol = (lane >> 4) * 8;
        #pragma unroll
        for (int ks = 0; ks < 4; ks++) {
            ldsm_x4(smem_u32(&sm[arow * KP + ks * 16 + acol]),
                    qh[ks][0], qh[ks][1], qh[ks][2], qh[ks][3]);
            ldsm_x4(smem_u32(&sm[TILE_U16 + arow * KP + ks * 16 + acol]),
                    ql[ks][0], ql[ks][1], ql[ks][2], ql[ks][3]);
        }
    }
    __syncthreads();

    float O[8][4] = {};
    float m0r = NEGBIG, m1r = NEGBIG, l0r = 0.f, l1r = 0.f;
    const float scale = 0.125f;

    const uint32_t stage_addr[2] = { smem_u32(sm), smem_u32(sm + STAGE_U16) };

    stage_tile(stage_addr[0], ((size_t)b * SS + t0 * 64) * 32, t);

    const int brow = (lane & 7) + ((lane >> 4) << 3);
    const int bco  = ((lane >> 3) & 1) * 8;
    const int vrow = lane & 15;
    const int vco  = (lane >> 4) * 8;

    for (int it = 0; it < nt; ++it) {
        const int st = it & 1;
        const unsigned short* Kh = sm + st * STAGE_U16;
        const unsigned short* Kl = Kh + TILE_U16;
        const unsigned short* Vh = Kh + 2 * TILE_U16;
        const unsigned short* Vl = Kh + 3 * TILE_U16;

        if (it + 1 < nt)
            stage_tile(stage_addr[st ^ 1], ((size_t)b * SS + (t0 + it + 1) * 64) * 32, t);
        if (t < 64) ms[t] = ((t0 + it) * 64 + t < nk) ? 0.f : NEGBIG;

        if (it + 1 < nt) asm volatile("cp.async.wait_group 1;");
        else             asm volatile("cp.async.wait_group 0;");
        __syncthreads();

        // --- S = Q K^T ---
        float S[8][4] = {};
        #pragma unroll
        for (int ks = 0; ks < 4; ks++) {
            #pragma unroll
            for (int pr = 0; pr < 4; pr++) {
                uint32_t bh0, bh1, bh2, bh3, bl0, bl1, bl2, bl3;
                ldsm_x4(smem_u32(&Kh[(pr * 16 + brow) * KP + ks * 16 + bco]),
                        bh0, bh1, bh2, bh3);
                ldsm_x4(smem_u32(&Kl[(pr * 16 + brow) * KP + ks * 16 + bco]),
                        bl0, bl1, bl2, bl3);
                float* s0 = S[pr * 2];
                float* s1 = S[pr * 2 + 1];
                mma_bf16(s0, qh[ks][0], qh[ks][1], qh[ks][2], qh[ks][3], bh0, bh1);
                mma_bf16(s0, qh[ks][0], qh[ks][1], qh[ks][2], qh[ks][3], bl0, bl1);
                mma_bf16(s0, ql[ks][0], ql[ks][1], ql[ks][2], ql[ks][3], bh0, bh1);
                mma_bf16(s1, qh[ks][0], qh[ks][1], qh[ks][2], qh[ks][3], bh2, bh3);
                mma_bf16(s1, qh[ks][0], qh[ks][1], qh[ks][2], qh[ks][3], bl2, bl3);
                mma_bf16(s1, ql[ks][0], ql[ks][1], ql[ks][2], ql[ks][3], bh2, bh3);
            }
        }

        // --- online softmax (finite sentinel, no guards) ---
        float rmax0 = NEGBIG, rmax1 = NEGBIG;
        #pragma unroll
        for (int na = 0; na < 8; na++) {
            int col = na * 8 + (lane & 3) * 2;
            float ma = ms[col], mb = ms[col + 1];
            S[na][0] = S[na][0] * scale + ma;
            S[na][1] = S[na][1] * scale + mb;
            S[na][2] = S[na][2] * scale + ma;
            S[na][3] = S[na][3] * scale + mb;
            rmax0 = fmaxf(rmax0, fmaxf(S[na][0], S[na][1]));
            rmax1 = fmaxf(rmax1, fmaxf(S[na][2], S[na][3]));
        }
        rmax0 = fmaxf(rmax0, __shfl_xor_sync(0xffffffffu, rmax0, 1));
        rmax0 = fmaxf(rmax0, __shfl_xor_sync(0xffffffffu, rmax0, 2));
        rmax1 = fmaxf(rmax1, __shfl_xor_sync(0xffffffffu, rmax1, 1));
        rmax1 = fmaxf(rmax1, __shfl_xor_sync(0xffffffffu, rmax1, 2));

        float nm0 = fmaxf(m0r, rmax0), nm1 = fmaxf(m1r, rmax1);
        float f0 = __expf(m0r - nm0);
        float f1 = __expf(m1r - nm1);
        float rs0 = 0.f, rs1 = 0.f;
        #pragma unroll
        for (int na = 0; na < 8; na++) {
            float p0 = __expf(S[na][0] - nm0);
            float p1 = __expf(S[na][1] - nm0);
            float p2 = __expf(S[na][2] - nm1);
            float p3 = __expf(S[na][3] - nm1);
            S[na][0] = p0; S[na][1] = p1; S[na][2] = p2; S[na][3] = p3;
            rs0 += p0 + p1; rs1 += p2 + p3;
        }
        rs0 += __shfl_xor_sync(0xffffffffu, rs0, 1);
        rs0 += __shfl_xor_sync(0xffffffffu, rs0, 2);
        rs1 += __shfl_xor_sync(0xffffffffu, rs1, 1);
        rs1 += __shfl_xor_sync(0xffffffffu, rs1, 2);
        l0r = l0r * f0 + rs0;  m0r = nm0;
        l1r = l1r * f1 + rs1;  m1r = nm1;

        #pragma unroll
        for (int na = 0; na < 8; na++) {
            O[na][0] *= f0; O[na][1] *= f0;
            O[na][2] *= f1; O[na][3] *= f1;
        }

        // --- O += P V ---
        #pragma unroll
        for (int kk = 0; kk < 4; kk++) {
            uint32_t ph[4], pl[4];
            split_pair(S[2 * kk][0],     S[2 * kk][1],     ph[0], pl[0]);
            split_pair(S[2 * kk][2],     S[2 * kk][3],     ph[1], pl[1]);
            split_pair(S[2 * kk + 1][0], S[2 * kk + 1][1], ph[2], pl[2]);
            split_pair(S[2 * kk + 1][2], S[2 * kk + 1][3], ph[3], pl[3]);
            #pragma unroll
            for (int pr = 0; pr < 4; pr++) {
                uint32_t bh0, bh1, bh2, bh3, bl0, bl1, bl2, bl3;
                ldsm_x4_t(smem_u32(&Vh[(kk * 16 + vrow) * KP + pr * 16 + vco]),
                          bh0, bh1, bh2, bh3);
                ldsm_x4_t(smem_u32(&Vl[(kk * 16 + vrow) * KP + pr * 16 + vco]),
                          bl0, bl1, bl2, bl3);
                float* o0 = O[pr * 2];
                float* o1 = O[pr * 2 + 1];
                mma_bf16(o0, ph[0], ph[1], ph[2], ph[3], bh0, bh1);
                mma_bf16(o0, ph[0], ph[1], ph[2], ph[3], bl0, bl1);
                mma_bf16(o0, pl[0], pl[1], pl[2], pl[3], bh0, bh1);
                mma_bf16(o1, ph[0], ph[1], ph[2], ph[3], bh2, bh3);
                mma_bf16(o1, ph[0], ph[1], ph[2], ph[3], bl2, bl3);
                mma_bf16(o1, pl[0], pl[1], pl[2], pl[3], bh2, bh3);
            }
        }
        __syncthreads();
    }

    // --- store UNNORMALIZED partial + (m,l) to slot ---
    int row0 = q0 + warp * 16 + (lane >> 2);
    float* Op = g_Op[slot];
    #pragma unroll
    for (int na = 0; na < 8; na++) {
        int col = na * 8 + (lane & 3) * 2;
        *(float2*)&Op[((size_t)b * SS + row0) * DD + col] =
            make_float2(O[na][0], O[na][1]);
        *(float2*)&Op[((size_t)b * SS + row0 + 8) * DD + col] =
            make_float2(O[na][2], O[na][3]);
    }
    if ((lane & 3) == 0) {
        size_t r = (size_t)b * SS + row0;
        g_mp[slot][r] = m0r;     g_lp[slot][r] = l0r;
        g_mp[slot][r + 8] = m1r; g_lp[slot][r + 8] = l1r;
    }
}

__global__ __launch_bounds__(128, 3) void attn_kernel()
{
    extern __shared__ unsigned short sm[];
    float* ms = (float*)(sm + 2 * STAGE_U16);

    const int c = blockIdx.x;

    int Tb[BB], cum[BB + 1];
    cum[0] = 0;
    #pragma unroll
    for (int b = 0; b < BB; b++) {
        Tb[b] = (g_kcnt[b] + 63) >> 6;
        cum[b + 1] = cum[b] + 32 * Tb[b];
    }
    const int total = cum[BB];
    const int W = (total + NCTA - 1) / NCTA;

    int g = c * W;
    int g1 = g + W;
    if (g1 > total) g1 = total;

    while (g < g1) {
        int b = 0;
        while (g >= cum[b + 1]) b++;
        const int rel = g - cum[b];
        const int qi = rel / Tb[b];
        const int lt = rel - qi * Tb[b];
        const int P0 = cum[b] + qi * Tb[b];
        int run = Tb[b] - lt;
        if (run > g1 - g) run = g1 - g;
        int slot = c - P0 / W;
        if (slot > NSLOT - 1) slot = NSLOT - 1;   // defensive
        flash_segment(sm, ms, b, qi * 64, lt, run, g_kcnt[b], slot);
        g += run;
    }
}

// ---------------------------------------------------------------------------
// combine split-KV partials (NSLOT-way); zero slots contribute 0 exactly
// ---------------------------------------------------------------------------
__global__ void combine_kernel(float* __restrict__ out) {
    int base = blockIdx.x * 512 + threadIdx.x;
    #pragma unroll
    for (int u = 0; u < 2; u++) {
        int idx = base + u * 256;
        int row = idx >> 4;
        float m[NSLOT], M = NEGBIG;
        #pragma unroll
        for (int s = 0; s < NSLOT; s++) {
            m[s] = g_mp[s][row];
            M = fmaxf(M, m[s]);
        }
        float wgt[NSLOT], denom = 0.f;
        #pragma unroll
        for (int s = 0; s < NSLOT; s++) {
            wgt[s] = __expf(m[s] - M);
            denom += wgt[s] * g_lp[s][row];
        }
        float inv = 1.f / denom;
        float4 r = make_float4(0.f, 0.f, 0.f, 0.f);
        #pragma unroll
        for (int s = 0; s < NSLOT; s++) {
            float a = wgt[s] * inv;
            float4 o = reinterpret_cast<const float4*>(g_Op[s])[idx];
            r.x += o.x * a; r.y += o.y * a; r.z += o.z * a; r.w += o.w * a;
        }
        reinterpret_cast<float4*>(out)[idx] = r;
    }
}

// ---------------------------------------------------------------------------
// Launch
// ---------------------------------------------------------------------------
extern "C" void kernel_launch(void* const* d_in, const int* in_sizes, int n_in,
                              void* d_out, int out_size) {
    const float* x  = (const float*)d_in[0];
    const float* Wq = (const float*)d_in[1];
    const float* bq = (const float*)d_in[2];
    const float* Wk = (const float*)d_in[3];
    const float* bk = (const float*)d_in[4];
    const float* Wv = (const float*)d_in[5];
    const float* bv = (const float*)d_in[6];
    const int*   pm = (const int*)d_in[7];
    float* out = (float*)d_out;

    prep_kernel<<<WBLK + BB, 256>>>(Wq, Wk, Wv, pm);

    cudaFuncSetAttribute(proj_kernel, cudaFuncAttributeMaxDynamicSharedMemorySize,
                         PROJ_SMEM_BYTES);
    proj_kernel<<<dim3(SS / 64, BB, 2), 256, PROJ_SMEM_BYTES>>>(x, bq, bk, bv);

    cudaFuncSetAttribute(attn_kernel, cudaFuncAttributeMaxDynamicSharedMemorySize,
                         ATTN_SMEM_BYTES);
    attn_kernel<<<NCTA, 128, ATTN_SMEM_BYTES>>>();

    combine_kernel<<<BB * SS * DD / 8 / 256, 256>>>(out);
}

// round 15
// speedup vs baseline: 1.0344x; 1.0163x over previous
#include <cuda_runtime.h>
#include <cstdint>
#include <math.h>

#define BB 8
#define SS 2048
#define EE 1024
#define DD 64
#define NSLOT 4             // split-KV partial slots (persistent scheduler)
#define NCTA 444            // persistent attn grid = 148 SMs x 3 CTAs
#define NEGBIG (-1.0e30f)   // finite -inf sentinel
#define WBLK 384            // prep: W-split blocks (3*64*512/256)

// q (all rows, scattered) and k,v (COMPACTED rows) as bf16 hi/lo planes
__device__ unsigned int g_qh[BB * SS * DD / 2];
__device__ unsigned int g_ql[BB * SS * DD / 2];
__device__ unsigned int g_kh[BB * SS * DD / 2];
__device__ unsigned int g_kl[BB * SS * DD / 2];
__device__ unsigned int g_vh[BB * SS * DD / 2];
__device__ unsigned int g_vl[BB * SS * DD / 2];

// W planes (bf16 hi/lo), [mat][n][k/2] u32
__device__ unsigned int g_Wh[3 * 64 * 512];
__device__ unsigned int g_Wl[3 * 64 * 512];

// mask compaction
__device__ int g_kidx[BB][SS];
__device__ int g_midx[BB][SS];
__device__ int g_kcnt[BB];

// split-KV partials (zero-init; unused slots contribute exactly 0 in combine)
__device__ float g_Op[NSLOT][BB * SS * DD];
__device__ float g_mp[NSLOT][BB * SS];
__device__ float g_lp[NSLOT][BB * SS];

// ---------------------------------------------------------------------------
// helpers
// ---------------------------------------------------------------------------
__device__ __forceinline__ uint32_t smem_u32(const void* p) {
    return (uint32_t)__cvta_generic_to_shared(p);
}

__device__ __forceinline__ void ldsm_x4(uint32_t addr, uint32_t& r0, uint32_t& r1,
                                        uint32_t& r2, uint32_t& r3) {
    asm volatile("ldmatrix.sync.aligned.m8n8.x4.shared.b16 {%0,%1,%2,%3}, [%4];"
                 : "=r"(r0), "=r"(r1), "=r"(r2), "=r"(r3) : "r"(addr));
}

__device__ __forceinline__ void ldsm_x4_t(uint32_t addr, uint32_t& r0, uint32_t& r1,
                                          uint32_t& r2, uint32_t& r3) {
    asm volatile("ldmatrix.sync.aligned.m8n8.x4.trans.shared.b16 {%0,%1,%2,%3}, [%4];"
                 : "=r"(r0), "=r"(r1), "=r"(r2), "=r"(r3) : "r"(addr));
}

__device__ __forceinline__ void mma_bf16(float c[4],
                                         uint32_t a0, uint32_t a1, uint32_t a2, uint32_t a3,
                                         uint32_t b0, uint32_t b1) {
    asm volatile("mma.sync.aligned.m16n8k16.row.col.f32.bf16.bf16.f32 "
                 "{%0,%1,%2,%3}, {%4,%5,%6,%7}, {%8,%9}, {%0,%1,%2,%3};"
                 : "+f"(c[0]), "+f"(c[1]), "+f"(c[2]), "+f"(c[3])
                 : "r"(a0), "r"(a1), "r"(a2), "r"(a3), "r"(b0), "r"(b1));
}

__device__ __forceinline__ uint32_t pack2(float x0, float x1) {
    uint32_t h;
    asm("cvt.rn.bf16x2.f32 %0, %1, %2;" : "=r"(h) : "f"(x1), "f"(x0));
    return h;
}

__device__ __forceinline__ void split_pair(float x0, float x1, uint32_t& hi, uint32_t& lo) {
    hi = pack2(x0, x1);
    float h0 = __uint_as_float(hi << 16);
    float h1 = __uint_as_float(hi & 0xffff0000u);
    lo = pack2(x0 - h0, x1 - h1);
}

__device__ __forceinline__ void cp16(uint32_t s, const void* g) {
    asm volatile("cp.async.cg.shared.global [%0], [%1], 16;" :: "r"(s), "l"(g));
}

// ---------------------------------------------------------------------------
// fused prep: blocks < WBLK split W; blocks >= WBLK build per-batch compaction
// ---------------------------------------------------------------------------
__global__ void prep_kernel(const float* __restrict__ Wq, const float* __restrict__ Wk,
                            const float* __restrict__ Wv, const int* __restrict__ mask) {
    if (blockIdx.x < WBLK) {
        int idx = blockIdx.x * 256 + threadIdx.x;   // < 98304 = 3*64*512
        int mat = idx >> 15;
        int off = idx & 32767;
        const float* W = (mat == 0) ? Wq : (mat == 1) ? Wk : Wv;
        float2 v = reinterpret_cast<const float2*>(W)[off];
        uint32_t h, l;
        split_pair(v.x, v.y, h, l);
        g_Wh[idx] = h;
        g_Wl[idx] = l;
        return;
    }
    const int b = blockIdx.x - WBLK;
    const int t = threadIdx.x;
    __shared__ int wsum[8];
    const int* mrow = mask + (size_t)b * SS;

    int um[8], loc[8], cnt = 0;
    #pragma unroll
    for (int j = 0; j < 8; j++) {
        int s = t * 8 + j;
        um[j] = (mrow[s] == 0);
        loc[j] = cnt;
        cnt += um[j];
    }
    const int lane = t & 31, w = t >> 5;
    int inc = cnt;
    #pragma unroll
    for (int off = 1; off < 32; off <<= 1) {
        int n = __shfl_up_sync(0xffffffffu, inc, off);
        if (lane >= off) inc += n;
    }
    if (lane == 31) wsum[w] = inc;
    __syncthreads();
    int wbase = 0;
    #pragma unroll
    for (int i = 0; i < 8; i++)
        if (i < w) wbase += wsum[i];
    const int base = wbase + inc - cnt;
    #pragma unroll
    for (int j = 0; j < 8; j++) {
        int s = t * 8 + j;
        int u = base + loc[j];
        if (um[j]) g_kidx[b][u] = s;
        else       g_midx[b][s - u] = s;
    }
    if (t == 255) g_kcnt[b] = base + cnt;
}

// ---------------------------------------------------------------------------
// Projection. Warp layout 2M x 4N (wm covers 32 rows = 2 m-atoms, wn covers
// 16 cols): B(W) ldsm per slab halves vs 4Mx2N. BM=64, BK=32, 256 threads.
// W planes via cp.async double-buffer; x via f32 register prefetch + split.
// ---------------------------------------------------------------------------
#define QP 40
#define XPL (64 * QP)
#define XSTG (2 * XPL)
#define WBASE (2 * XSTG)
#define PROJ_SMEM_BYTES ((WBASE + 2 * 6 * XPL) * 2)

template<int NMAT>
__device__ __forceinline__ void proj_body(
    unsigned short* qsm, const float* __restrict__ x,
    const float* __restrict__ bq, const float* __restrict__ bk,
    const float* __restrict__ bv,
    int b, int j0, int cnt, const int* __restrict__ list)
{
    constexpr int WSTGP = 2 * NMAT;

    const int t = threadIdx.x;
    const int warp = t >> 5, lane = t & 31;
    const int wm = warp >> 2;        // 0..1: rows wm*32 .. +32 (2 m-atoms)
    const int wn = warp & 3;         // 0..3: cols wn*16 .. +16 (2 n-atoms)

    float acc[NMAT][2][2][4] = {};   // [mat][matom][natom][reg]

    const int arow = (lane & 15);    // + wm*32 + ma*16
    const int acol = (lane >> 4) * 8;
    const int brow = (lane & 7) + ((lane >> 4) << 3);
    const int bcol = ((lane >> 3) & 1) * 8;

    const int xr = t >> 2;
    const int xc = (t & 3) * 8;

    int jg = j0 + xr;
    if (jg > cnt - 1) jg = cnt - 1;
    const float* xrow = x + ((size_t)b * SS + list[jg]) * EE;

    auto issue_w = [&](int s, int slab) {
        #pragma unroll
        for (int i = 0; i < 2 * NMAT; i++) {
            int chunk = t + i * 256;
            int p = chunk >> 8, c = chunk & 255;
            int row = c >> 2, c4 = c & 3;
            uint32_t dst = smem_u32(&qsm[WBASE + (s * WSTGP + p) * XPL + row * QP + c4 * 8]);
            const unsigned int* srcp = (p & 1) ? g_Wl : g_Wh;
            cp16(dst, srcp + ((size_t)(p >> 1) * 32768
                              + (size_t)row * 512 + slab * 16 + c4 * 4));
        }
        asm volatile("cp.async.commit_group;");
    };

    auto sts_x = [&](int s, float4 a0, float4 a1) {
        unsigned short* Xh = qsm + s * XSTG;
        unsigned short* Xl = Xh + XPL;
        uint32_t h0, l0, h1, l1, h2, l2, h3, l3;
        split_pair(a0.x, a0.y, h0, l0);
        split_pair(a0.z, a0.w, h1, l1);
        split_pair(a1.x, a1.y, h2, l2);
        split_pair(a1.z, a1.w, h3, l3);
        *reinterpret_cast<uint4*>(&Xh[xr * QP + xc]) = make_uint4(h0, h1, h2, h3);
        *reinterpret_cast<uint4*>(&Xl[xr * QP + xc]) = make_uint4(l0, l1, l2, l3);
    };

    issue_w(0, 0);
    {
        float4 a0 = *reinterpret_cast<const float4*>(&xrow[xc]);
        float4 a1 = *reinterpret_cast<const float4*>(&xrow[xc + 4]);
        sts_x(0, a0, a1);
    }
    float4 xa0 = *reinterpret_cast<const float4*>(&xrow[32 + xc]);
    float4 xa1 = *reinterpret_cast<const float4*>(&xrow[32 + xc + 4]);

    const int NI = EE / 32;
    for (int i = 0; i < NI; i++) {
        const int s = i & 1;

        asm volatile("cp.async.wait_group 0;");
        __syncthreads();

        if (i + 1 < NI) {
            issue_w(s ^ 1, i + 1);
            sts_x(s ^ 1, xa0, xa1);
            if (i + 2 < NI) {
                int kn = (i + 2) * 32;
                xa0 = *reinterpret_cast<const float4*>(&xrow[kn + xc]);
                xa1 = *reinterpret_cast<const float4*>(&xrow[kn + xc + 4]);
            }
        }

        const unsigned short* Xh = qsm + s * XSTG;
        const unsigned short* Xl = Xh + XPL;
        const unsigned short* Wb = qsm + WBASE + s * WSTGP * XPL;

        #pragma unroll
        for (int ks = 0; ks < 2; ks++) {
            // A fragments: 2 m-atoms x hi/lo
            uint32_t ah[2][4], al[2][4];
            #pragma unroll
            for (int ma = 0; ma < 2; ma++) {
                int r = wm * 32 + ma * 16 + arow;
                ldsm_x4(smem_u32(&Xh[r * QP + ks * 16 + acol]),
                        ah[ma][0], ah[ma][1], ah[ma][2], ah[ma][3]);
                ldsm_x4(smem_u32(&Xl[r * QP + ks * 16 + acol]),
                        al[ma][0], al[ma][1], al[ma][2], al[ma][3]);
            }
            #pragma unroll
            for (int mm = 0; mm < NMAT; mm++) {
                const unsigned short* Wh = Wb + (mm * 2) * XPL;
                const unsigned short* Wl = Wh + XPL;
                uint32_t bh0, bh1, bh2, bh3, bl0, bl1, bl2, bl3;
                ldsm_x4(smem_u32(&Wh[(wn * 16 + brow) * QP + ks * 16 + bcol]),
                        bh0, bh1, bh2, bh3);
                ldsm_x4(smem_u32(&Wl[(wn * 16 + brow) * QP + ks * 16 + bcol]),
                        bl0, bl1, bl2, bl3);
                #pragma unroll
                for (int ma = 0; ma < 2; ma++) {
                    float* c0 = acc[mm][ma][0];
                    float* c1 = acc[mm][ma][1];
                    mma_bf16(c0, ah[ma][0], ah[ma][1], ah[ma][2], ah[ma][3], bh0, bh1);
                    mma_bf16(c0, ah[ma][0], ah[ma][1], ah[ma][2], ah[ma][3], bl0, bl1);
                    mma_bf16(c0, al[ma][0], al[ma][1], al[ma][2], al[ma][3], bh0, bh1);
                    mma_bf16(c1, ah[ma][0], ah[ma][1], ah[ma][2], ah[ma][3], bh2, bh3);
                    mma_bf16(c1, ah[ma][0], ah[ma][1], ah[ma][2], ah[ma][3], bl2, bl3);
                    mma_bf16(c1, al[ma][0], al[ma][1], al[ma][2], al[ma][3], bh2, bh3);
                }
            }
        }
    }

    // epilogue: Q (mm=0) scattered; K/V (mm=1,2) compacted. 2Mx4N mapping.
    #pragma unroll
    for (int ma = 0; ma < 2; ma++) {
        int jr0 = j0 + wm * 32 + ma * 16 + (lane >> 2);
        int jr8 = jr0 + 8;
        if (jr0 > cnt - 1) jr0 = cnt - 1;
        if (jr8 > cnt - 1) jr8 = cnt - 1;
        const size_t qrow0 = (size_t)b * SS + list[jr0];
        const size_t qrow8 = (size_t)b * SS + list[jr8];
        #pragma unroll
        for (int mm = 0; mm < NMAT; mm++) {
            const float* bias = (mm == 0) ? bq : (mm == 1) ? bk : bv;
            unsigned int* gh = (mm == 0) ? g_qh : (mm == 1) ? g_kh : g_vh;
            unsigned int* gl = (mm == 0) ? g_ql : (mm == 1) ? g_kl : g_vl;
            size_t r0, r8;
            if (mm == 0) { r0 = qrow0; r8 = qrow8; }
            else {
                r0 = (size_t)b * SS + j0 + wm * 32 + ma * 16 + (lane >> 2);
                r8 = r0 + 8;
            }
            #pragma unroll
            for (int na = 0; na < 2; na++) {
                int col = wn * 16 + na * 8 + (lane & 3) * 2;
                float b0 = bias[col], b1 = bias[col + 1];
                float c0 = acc[mm][ma][na][0] + b0, c1 = acc[mm][ma][na][1] + b1;
                float c2 = acc[mm][ma][na][2] + b0, c3 = acc[mm][ma][na][3] + b1;
                uint32_t h, l;
                split_pair(c0, c1, h, l);
                gh[r0 * 32 + col / 2] = h;
                gl[r0 * 32 + col / 2] = l;
                split_pair(c2, c3, h, l);
                gh[r8 * 32 + col / 2] = h;
                gl[r8 * 32 + col / 2] = l;
            }
        }
    }
}

__global__ __launch_bounds__(256, 2) void proj_kernel(
    const float* __restrict__ x,
    const float* __restrict__ bq, const float* __restrict__ bk,
    const float* __restrict__ bv)
{
    extern __shared__ unsigned short qsm[];
    const int b = blockIdx.y;
    const int j0 = blockIdx.x * 64;
    const int nk = g_kcnt[b];

    if (blockIdx.z == 0) {
        if (j0 >= nk) return;
        proj_body<3>(qsm, x, bq, bk, bv, b, j0, nk, g_kidx[b]);
    } else {
        const int nm = SS - nk;
        if (j0 >= nm || nm == 0) return;
        proj_body<1>(qsm, x, bq, bk, bv, b, j0, nm, g_midx[b]);
    }
}

// ---------------------------------------------------------------------------
// Flash attention, PERSISTENT scheduler (unchanged from R14 champion).
// ---------------------------------------------------------------------------
#define KP 72
#define TILE_U16 (64 * KP)
#define STAGE_U16 (4 * TILE_U16)
#define ATTN_SMEM_BYTES (2 * STAGE_U16 * 2 + 64 * 4)

__device__ __forceinline__ void stage_tile(uint32_t sbase, size_t gbase, int t) {
    #pragma unroll
    for (int i = 0; i < 4; i++) {
        int chunk = t + i * 128;
        int r = chunk >> 3, c = chunk & 7;
        uint32_t soff = (uint32_t)(r * KP + c * 8) * 2;
        size_t goff = (size_t)r * 32 + c * 4;
        cp16(sbase + soff,                     g_kh + gbase + goff);
        cp16(sbase + TILE_U16 * 2 + soff,      g_kl + gbase + goff);
        cp16(sbase + 2 * TILE_U16 * 2 + soff,  g_vh + gbase + goff);
        cp16(sbase + 3 * TILE_U16 * 2 + soff,  g_vl + gbase + goff);
    }
    asm volatile("cp.async.commit_group;");
}

__device__ __forceinline__ void flash_segment(
    unsigned short* sm, float* ms, int b, int q0, int t0, int nt, int nk, int slot)
{
    const int t = threadIdx.x, warp = t >> 5, lane = t & 31;

    __syncthreads();

    {
        uint32_t s0 = smem_u32(sm);
        size_t gq = ((size_t)b * SS + q0) * 32;
        #pragma unroll
        for (int i = 0; i < 4; i++) {
            int chunk = t + i * 128;
            int r = chunk >> 3, c = chunk & 7;
            uint32_t soff = (uint32_t)(r * KP + c * 8) * 2;
            size_t goff = (size_t)r * 32 + c * 4;
            cp16(s0 + soff,                g_qh + gq + goff);
            cp16(s0 + TILE_U16 * 2 + soff, g_ql + gq + goff);
        }
        asm volatile("cp.async.commit_group;");
        asm volatile("cp.async.wait_group 0;");
        __syncthreads();
    }

    uint32_t qh[4][4], ql[4][4];
    {
        const int arow = warp * 16 + (lane & 15);
        const int acol = (lane >> 4) * 8;
        #pragma unroll
        for (int ks = 0; ks < 4; ks++) {
            ldsm_x4(smem_u32(&sm[arow * KP + ks * 16 + acol]),
                    qh[ks][0], qh[ks][1], qh[ks][2], qh[ks][3]);
            ldsm_x4(smem_u32(&sm[TILE_U16 + arow * KP + ks * 16 + acol]),
                    ql[ks][0], ql[ks][1], ql[ks][2], ql[ks][3]);
        }
    }
    __syncthreads();

    float O[8][4] = {};
    float m0r = NEGBIG, m1r = NEGBIG, l0r = 0.f, l1r = 0.f;
    const float scale = 0.125f;

    const uint32_t stage_addr[2] = { smem_u32(sm), smem_u32(sm + STAGE_U16) };

    stage_tile(stage_addr[0], ((size_t)b * SS + t0 * 64) * 32, t);

    const int brow = (lane & 7) + ((lane >> 4) << 3);
    const int bco  = ((lane >> 3) & 1) * 8;
    const int vrow = lane & 15;
    const int vco  = (lane >> 4) * 8;

    for (int it = 0; it < nt; ++it) {
        const int st = it & 1;
        const unsigned short* Kh = sm + st * STAGE_U16;
        const unsigned short* Kl = Kh + TILE_U16;
        const unsigned short* Vh = Kh + 2 * TILE_U16;
        const unsigned short* Vl = Kh + 3 * TILE_U16;

        if (it + 1 < nt)
            stage_tile(stage_addr[st ^ 1], ((size_t)b * SS + (t0 + it + 1) * 64) * 32, t);
        if (t < 64) ms[t] = ((t0 + it) * 64 + t < nk) ? 0.f : NEGBIG;

        if (it + 1 < nt) asm volatile("cp.async.wait_group 1;");
        else             asm volatile("cp.async.wait_group 0;");
        __syncthreads();

        float S[8][4] = {};
        #pragma unroll
        for (int ks = 0; ks < 4; ks++) {
            #pragma unroll
            for (int pr = 0; pr < 4; pr++) {
                uint32_t bh0, bh1, bh2, bh3, bl0, bl1, bl2, bl3;
                ldsm_x4(smem_u32(&Kh[(pr * 16 + brow) * KP + ks * 16 + bco]),
                        bh0, bh1, bh2, bh3);
                ldsm_x4(smem_u32(&Kl[(pr * 16 + brow) * KP + ks * 16 + bco]),
                        bl0, bl1, bl2, bl3);
                float* s0 = S[pr * 2];
                float* s1 = S[pr * 2 + 1];
                mma_bf16(s0, qh[ks][0], qh[ks][1], qh[ks][2], qh[ks][3], bh0, bh1);
                mma_bf16(s0, qh[ks][0], qh[ks][1], qh[ks][2], qh[ks][3], bl0, bl1);
                mma_bf16(s0, ql[ks][0], ql[ks][1], ql[ks][2], ql[ks][3], bh0, bh1);
                mma_bf16(s1, qh[ks][0], qh[ks][1], qh[ks][2], qh[ks][3], bh2, bh3);
                mma_bf16(s1, qh[ks][0], qh[ks][1], qh[ks][2], qh[ks][3], bl2, bl3);
                mma_bf16(s1, ql[ks][0], ql[ks][1], ql[ks][2], ql[ks][3], bh2, bh3);
            }
        }

        float rmax0 = NEGBIG, rmax1 = NEGBIG;
        #pragma unroll
        for (int na = 0; na < 8; na++) {
            int col = na * 8 + (lane & 3) * 2;
            float ma = ms[col], mb = ms[col + 1];
            S[na][0] = S[na][0] * scale + ma;
            S[na][1] = S[na][1] * scale + mb;
            S[na][2] = S[na][2] * scale + ma;
            S[na][3] = S[na][3] * scale + mb;
            rmax0 = fmaxf(rmax0, fmaxf(S[na][0], S[na][1]));
            rmax1 = fmaxf(rmax1, fmaxf(S[na][2], S[na][3]));
        }
        rmax0 = fmaxf(rmax0, __shfl_xor_sync(0xffffffffu, rmax0, 1));
        rmax0 = fmaxf(rmax0, __shfl_xor_sync(0xffffffffu, rmax0, 2));
        rmax1 = fmaxf(rmax1, __shfl_xor_sync(0xffffffffu, rmax1, 1));
        rmax1 = fmaxf(rmax1, __shfl_xor_sync(0xffffffffu, rmax1, 2));

        float nm0 = fmaxf(m0r, rmax0), nm1 = fmaxf(m1r, rmax1);
        float f0 = __expf(m0r - nm0);
        float f1 = __expf(m1r - nm1);
        float rs0 = 0.f, rs1 = 0.f;
        #pragma unroll
        for (int na = 0; na < 8; na++) {
            float p0 = __expf(S[na][0] - nm0);
            float p1 = __expf(S[na][1] - nm0);
            float p2 = __expf(S[na][2] - nm1);
            float p3 = __expf(S[na][3] - nm1);
            S[na][0] = p0; S[na][1] = p1; S[na][2] = p2; S[na][3] = p3;
            rs0 += p0 + p1; rs1 += p2 + p3;
        }
        rs0 += __shfl_xor_sync(0xffffffffu, rs0, 1);
        rs0 += __shfl_xor_sync(0xffffffffu, rs0, 2);
        rs1 += __shfl_xor_sync(0xffffffffu, rs1, 1);
        rs1 += __shfl_xor_sync(0xffffffffu, rs1, 2);
        l0r = l0r * f0 + rs0;  m0r = nm0;
        l1r = l1r * f1 + rs1;  m1r = nm1;

        #pragma unroll
        for (int na = 0; na < 8; na++) {
            O[na][0] *= f0; O[na][1] *= f0;
            O[na][2] *= f1; O[na][3] *= f1;
        }

        #pragma unroll
        for (int kk = 0; kk < 4; kk++) {
            uint32_t ph[4], pl[4];
            split_pair(S[2 * kk][0],     S[2 * kk][1],     ph[0], pl[0]);
            split_pair(S[2 * kk][2],     S[2 * kk][3],     ph[1], pl[1]);
            split_pair(S[2 * kk + 1][0], S[2 * kk + 1][1], ph[2], pl[2]);
            split_pair(S[2 * kk + 1][2], S[2 * kk + 1][3], ph[3], pl[3]);
            #pragma unroll
            for (int pr = 0; pr < 4; pr++) {
                uint32_t bh0, bh1, bh2, bh3, bl0, bl1, bl2, bl3;
                ldsm_x4_t(smem_u32(&Vh[(kk * 16 + vrow) * KP + pr * 16 + vco]),
                          bh0, bh1, bh2, bh3);
                ldsm_x4_t(smem_u32(&Vl[(kk * 16 + vrow) * KP + pr * 16 + vco]),
                          bl0, bl1, bl2, bl3);
                float* o0 = O[pr * 2];
                float* o1 = O[pr * 2 + 1];
                mma_bf16(o0, ph[0], ph[1], ph[2], ph[3], bh0, bh1);
                mma_bf16(o0, ph[0], ph[1], ph[2], ph[3], bl0, bl1);
                mma_bf16(o0, pl[0], pl[1], pl[2], pl[3], bh0, bh1);
                mma_bf16(o1, ph[0], ph[1], ph[2], ph[3], bh2, bh3);
                mma_bf16(o1, ph[0], ph[1], ph[2], ph[3], bl2, bl3);
                mma_bf16(o1, pl[0], pl[1], pl[2], pl[3], bh2, bh3);
            }
        }
        __syncthreads();
    }

    int row0 = q0 + warp * 16 + (lane >> 2);
    float* Op = g_Op[slot];
    #pragma unroll
    for (int na = 0; na < 8; na++) {
        int col = na * 8 + (lane & 3) * 2;
        *(float2*)&Op[((size_t)b * SS + row0) * DD + col] =
            make_float2(O[na][0], O[na][1]);
        *(float2*)&Op[((size_t)b * SS + row0 + 8) * DD + col] =
            make_float2(O[na][2], O[na][3]);
    }
    if ((lane & 3) == 0) {
        size_t r = (size_t)b * SS + row0;
        g_mp[slot][r] = m0r;     g_lp[slot][r] = l0r;
        g_mp[slot][r + 8] = m1r; g_lp[slot][r + 8] = l1r;
    }
}

__global__ __launch_bounds__(128, 3) void attn_kernel()
{
    extern __shared__ unsigned short sm[];
    float* ms = (float*)(sm + 2 * STAGE_U16);

    const int c = blockIdx.x;

    int Tb[BB], cum[BB + 1];
    cum[0] = 0;
    #pragma unroll
    for (int b = 0; b < BB; b++) {
        Tb[b] = (g_kcnt[b] + 63) >> 6;
        cum[b + 1] = cum[b] + 32 * Tb[b];
    }
    const int total = cum[BB];
    const int W = (total + NCTA - 1) / NCTA;

    int g = c * W;
    int g1 = g + W;
    if (g1 > total) g1 = total;

    while (g < g1) {
        int b = 0;
        while (g >= cum[b + 1]) b++;
        const int rel = g - cum[b];
        const int qi = rel / Tb[b];
        const int lt = rel - qi * Tb[b];
        const int P0 = cum[b] + qi * Tb[b];
        int run = Tb[b] - lt;
        if (run > g1 - g) run = g1 - g;
        int slot = c - P0 / W;
        if (slot > NSLOT - 1) slot = NSLOT - 1;   // defensive
        flash_segment(sm, ms, b, qi * 64, lt, run, g_kcnt[b], slot);
        g += run;
    }
}

// ---------------------------------------------------------------------------
// combine split-KV partials (NSLOT-way); zero slots contribute 0 exactly
// ---------------------------------------------------------------------------
__global__ void combine_kernel(float* __restrict__ out) {
    int base = blockIdx.x * 512 + threadIdx.x;
    #pragma unroll
    for (int u = 0; u < 2; u++) {
        int idx = base + u * 256;
        int row = idx >> 4;
        float m[NSLOT], M = NEGBIG;
        #pragma unroll
        for (int s = 0; s < NSLOT; s++) {
            m[s] = g_mp[s][row];
            M = fmaxf(M, m[s]);
        }
        float wgt[NSLOT], denom = 0.f;
        #pragma unroll
        for (int s = 0; s < NSLOT; s++) {
            wgt[s] = __expf(m[s] - M);
            denom += wgt[s] * g_lp[s][row];
        }
        float inv = 1.f / denom;
        float4 r = make_float4(0.f, 0.f, 0.f, 0.f);
        #pragma unroll
        for (int s = 0; s < NSLOT; s++) {
            float a = wgt[s] * inv;
            float4 o = reinterpret_cast<const float4*>(g_Op[s])[idx];
            r.x += o.x * a; r.y += o.y * a; r.z += o.z * a; r.w += o.w * a;
        }
        reinterpret_cast<float4*>(out)[idx] = r;
    }
}

// ---------------------------------------------------------------------------
// Launch
// ---------------------------------------------------------------------------
extern "C" void kernel_launch(void* const* d_in, const int* in_sizes, int n_in,
                              void* d_out, int out_size) {
    const float* x  = (const float*)d_in[0];
    const float* Wq = (const float*)d_in[1];
    const float* bq = (const float*)d_in[2];
    const float* Wk = (const float*)d_in[3];
    const float* bk = (const float*)d_in[4];
    const float* Wv = (const float*)d_in[5];
    const float* bv = (const float*)d_in[6];
    const int*   pm = (const int*)d_in[7];
    float* out = (float*)d_out;

    prep_kernel<<<WBLK + BB, 256>>>(Wq, Wk, Wv, pm);

    cudaFuncSetAttribute(proj_kernel, cudaFuncAttributeMaxDynamicSharedMemorySize,
                         PROJ_SMEM_BYTES);
    proj_kernel<<<dim3(SS / 64, BB, 2), 256, PROJ_SMEM_BYTES>>>(x, bq, bk, bv);

    cudaFuncSetAttribute(attn_kernel, cudaFuncAttributeMaxDynamicSharedMemorySize,
                         ATTN_SMEM_BYTES);
    attn_kernel<<<NCTA, 128, ATTN_SMEM_BYTES>>>();

    combine_kernel<<<BB * SS * DD / 8 / 256, 256>>>(out);
}

// round 16
// speedup vs baseline: 1.0384x; 1.0038x over previous
#include <cuda_runtime.h>
#include <cstdint>
#include <math.h>

#define BB 8
#define SS 2048
#define EE 1024
#define DD 64
#define NSLOT 4             // split-KV partial slots (persistent scheduler)
#define NCTA 444            // persistent attn grid = 148 SMs x 3 CTAs
#define NEGBIG (-1.0e30f)   // finite -inf sentinel
#define WBLK 384            // prep: W-split blocks (3*64*512/256)

// q (all rows, scattered) and k,v (COMPACTED rows) as bf16 hi/lo planes
__device__ unsigned int g_qh[BB * SS * DD / 2];
__device__ unsigned int g_ql[BB * SS * DD / 2];
__device__ unsigned int g_kh[BB * SS * DD / 2];
__device__ unsigned int g_kl[BB * SS * DD / 2];
__device__ unsigned int g_vh[BB * SS * DD / 2];
__device__ unsigned int g_vl[BB * SS * DD / 2];

// W planes (bf16 hi/lo), [mat][n][k/2] u32
__device__ unsigned int g_Wh[3 * 64 * 512];
__device__ unsigned int g_Wl[3 * 64 * 512];

// mask compaction
__device__ int g_kidx[BB][SS];
__device__ int g_midx[BB][SS];
__device__ int g_kcnt[BB];

// split-KV partials (zero-init; unused slots contribute exactly 0 in combine)
__device__ float g_Op[NSLOT][BB * SS * DD];
__device__ float g_mp[NSLOT][BB * SS];
__device__ float g_lp[NSLOT][BB * SS];

// ---------------------------------------------------------------------------
// helpers
// ---------------------------------------------------------------------------
__device__ __forceinline__ uint32_t smem_u32(const void* p) {
    return (uint32_t)__cvta_generic_to_shared(p);
}

__device__ __forceinline__ void ldsm_x4(uint32_t addr, uint32_t& r0, uint32_t& r1,
                                        uint32_t& r2, uint32_t& r3) {
    asm volatile("ldmatrix.sync.aligned.m8n8.x4.shared.b16 {%0,%1,%2,%3}, [%4];"
                 : "=r"(r0), "=r"(r1), "=r"(r2), "=r"(r3) : "r"(addr));
}

__device__ __forceinline__ void ldsm_x4_t(uint32_t addr, uint32_t& r0, uint32_t& r1,
                                          uint32_t& r2, uint32_t& r3) {
    asm volatile("ldmatrix.sync.aligned.m8n8.x4.trans.shared.b16 {%0,%1,%2,%3}, [%4];"
                 : "=r"(r0), "=r"(r1), "=r"(r2), "=r"(r3) : "r"(addr));
}

__device__ __forceinline__ void mma_bf16(float c[4],
                                         uint32_t a0, uint32_t a1, uint32_t a2, uint32_t a3,
                                         uint32_t b0, uint32_t b1) {
    asm volatile("mma.sync.aligned.m16n8k16.row.col.f32.bf16.bf16.f32 "
                 "{%0,%1,%2,%3}, {%4,%5,%6,%7}, {%8,%9}, {%0,%1,%2,%3};"
                 : "+f"(c[0]), "+f"(c[1]), "+f"(c[2]), "+f"(c[3])
                 : "r"(a0), "r"(a1), "r"(a2), "r"(a3), "r"(b0), "r"(b1));
}

__device__ __forceinline__ uint32_t pack2(float x0, float x1) {
    uint32_t h;
    asm("cvt.rn.bf16x2.f32 %0, %1, %2;" : "=r"(h) : "f"(x1), "f"(x0));
    return h;
}

__device__ __forceinline__ void split_pair(float x0, float x1, uint32_t& hi, uint32_t& lo) {
    hi = pack2(x0, x1);
    float h0 = __uint_as_float(hi << 16);
    float h1 = __uint_as_float(hi & 0xffff0000u);
    lo = pack2(x0 - h0, x1 - h1);
}

__device__ __forceinline__ void cp16(uint32_t s, const void* g) {
    asm volatile("cp.async.cg.shared.global [%0], [%1], 16;" :: "r"(s), "l"(g));
}

// ---------------------------------------------------------------------------
// fused prep: blocks < WBLK split W; blocks >= WBLK build per-batch compaction
// ---------------------------------------------------------------------------
__global__ void prep_kernel(const float* __restrict__ Wq, const float* __restrict__ Wk,
                            const float* __restrict__ Wv, const int* __restrict__ mask) {
    if (blockIdx.x < WBLK) {
        int idx = blockIdx.x * 256 + threadIdx.x;   // < 98304 = 3*64*512
        int mat = idx >> 15;
        int off = idx & 32767;
        const float* W = (mat == 0) ? Wq : (mat == 1) ? Wk : Wv;
        float2 v = reinterpret_cast<const float2*>(W)[off];
        uint32_t h, l;
        split_pair(v.x, v.y, h, l);
        g_Wh[idx] = h;
        g_Wl[idx] = l;
        return;
    }
    const int b = blockIdx.x - WBLK;
    const int t = threadIdx.x;
    __shared__ int wsum[8];
    const int* mrow = mask + (size_t)b * SS;

    int um[8], loc[8], cnt = 0;
    #pragma unroll
    for (int j = 0; j < 8; j++) {
        int s = t * 8 + j;
        um[j] = (mrow[s] == 0);
        loc[j] = cnt;
        cnt += um[j];
    }
    const int lane = t & 31, w = t >> 5;
    int inc = cnt;
    #pragma unroll
    for (int off = 1; off < 32; off <<= 1) {
        int n = __shfl_up_sync(0xffffffffu, inc, off);
        if (lane >= off) inc += n;
    }
    if (lane == 31) wsum[w] = inc;
    __syncthreads();
    int wbase = 0;
    #pragma unroll
    for (int i = 0; i < 8; i++)
        if (i < w) wbase += wsum[i];
    const int base = wbase + inc - cnt;
    #pragma unroll
    for (int j = 0; j < 8; j++) {
        int s = t * 8 + j;
        int u = base + loc[j];
        if (um[j]) g_kidx[b][u] = s;
        else       g_midx[b][s - u] = s;
    }
    if (t == 255) g_kcnt[b] = base + cnt;
}

// ---------------------------------------------------------------------------
// Projection. 2M x 4N warp layout; W planes on a 3-STAGE cp.async ring with
// end-of-body wait_group 1 (W[i+1] gets ~2 slabs of latency cover, published
// by the next top barrier). X planes 2-stage (STS path). One barrier/slab.
// ---------------------------------------------------------------------------
#define QP 40
#define XPL (64 * QP)                 // u16 per plane (5120 B)
#define XSTG (2 * XPL)                // X stage: hi+lo
#define WBASE (2 * XSTG)              // after 2 X stages
#define PROJ_SMEM_BYTES ((2 * 2 + 3 * 6) * XPL * 2)   // 110 KB (NMAT=3 sizing)

template<int NMAT>
__device__ __forceinline__ void proj_body(
    unsigned short* qsm, const float* __restrict__ x,
    const float* __restrict__ bq, const float* __restrict__ bk,
    const float* __restrict__ bv,
    int b, int j0, int cnt, const int* __restrict__ list)
{
    constexpr int WSTGP = 2 * NMAT;

    const int t = threadIdx.x;
    const int warp = t >> 5, lane = t & 31;
    const int wm = warp >> 2;        // 0..1: rows wm*32 .. +32 (2 m-atoms)
    const int wn = warp & 3;         // 0..3: cols wn*16 .. +16 (2 n-atoms)

    float acc[NMAT][2][2][4] = {};   // [mat][matom][natom][reg]

    const int arow = (lane & 15);
    const int acol = (lane >> 4) * 8;
    const int brow = (lane & 7) + ((lane >> 4) << 3);
    const int bcol = ((lane >> 3) & 1) * 8;

    const int xr = t >> 2;
    const int xc = (t & 3) * 8;

    int jg = j0 + xr;
    if (jg > cnt - 1) jg = cnt - 1;
    const float* xrow = x + ((size_t)b * SS + list[jg]) * EE;

    // W stage wst (0..2) for k-slab: 2*NMAT planes x 256 chunks of 16B
    auto issue_w = [&](int wst, int slab) {
        #pragma unroll
        for (int i = 0; i < 2 * NMAT; i++) {
            int chunk = t + i * 256;
            int p = chunk >> 8, c = chunk & 255;
            int row = c >> 2, c4 = c & 3;
            uint32_t dst = smem_u32(&qsm[WBASE + (wst * WSTGP + p) * XPL + row * QP + c4 * 8]);
            const unsigned int* srcp = (p & 1) ? g_Wl : g_Wh;
            cp16(dst, srcp + ((size_t)(p >> 1) * 32768
                              + (size_t)row * 512 + slab * 16 + c4 * 4));
        }
        asm volatile("cp.async.commit_group;");
    };

    auto sts_x = [&](int xst, float4 a0, float4 a1) {
        unsigned short* Xh = qsm + xst * XSTG;
        unsigned short* Xl = Xh + XPL;
        uint32_t h0, l0, h1, l1, h2, l2, h3, l3;
        split_pair(a0.x, a0.y, h0, l0);
        split_pair(a0.z, a0.w, h1, l1);
        split_pair(a1.x, a1.y, h2, l2);
        split_pair(a1.z, a1.w, h3, l3);
        *reinterpret_cast<uint4*>(&Xh[xr * QP + xc]) = make_uint4(h0, h1, h2, h3);
        *reinterpret_cast<uint4*>(&Xl[xr * QP + xc]) = make_uint4(l0, l1, l2, l3);
    };

    const int NI = EE / 32;   // 32 slabs

    // prologue: W0, W1 in flight; X0 staged; x regs hold slab 1
    issue_w(0, 0);
    issue_w(1, 1);
    {
        float4 a0 = *reinterpret_cast<const float4*>(&xrow[xc]);
        float4 a1 = *reinterpret_cast<const float4*>(&xrow[xc + 4]);
        sts_x(0, a0, a1);
    }
    float4 xa0 = *reinterpret_cast<const float4*>(&xrow[32 + xc]);
    float4 xa1 = *reinterpret_cast<const float4*>(&xrow[32 + xc + 4]);
    asm volatile("cp.async.wait_group 1;");   // W0 complete (W1 still flying)

    for (int i = 0; i < NI; i++) {
        __syncthreads();   // publishes W[i], X[i]; frees W stage (i+2)%3, X stage (i+1)&1

        if (i + 2 < NI) issue_w((i + 2) % 3, i + 2);
        if (i + 1 < NI) {
            sts_x((i + 1) & 1, xa0, xa1);
            if (i + 2 < NI) {
                int kn = (i + 2) * 32;
                xa0 = *reinterpret_cast<const float4*>(&xrow[kn + xc]);
                xa1 = *reinterpret_cast<const float4*>(&xrow[kn + xc + 4]);
            }
        }

        const unsigned short* Xh = qsm + (i & 1) * XSTG;
        const unsigned short* Xl = Xh + XPL;
        const unsigned short* Wb = qsm + WBASE + (i % 3) * WSTGP * XPL;

        #pragma unroll
        for (int ks = 0; ks < 2; ks++) {
            uint32_t ah[2][4], al[2][4];
            #pragma unroll
            for (int ma = 0; ma < 2; ma++) {
                int r = wm * 32 + ma * 16 + arow;
                ldsm_x4(smem_u32(&Xh[r * QP + ks * 16 + acol]),
                        ah[ma][0], ah[ma][1], ah[ma][2], ah[ma][3]);
                ldsm_x4(smem_u32(&Xl[r * QP + ks * 16 + acol]),
                        al[ma][0], al[ma][1], al[ma][2], al[ma][3]);
            }
            #pragma unroll
            for (int mm = 0; mm < NMAT; mm++) {
                const unsigned short* Wh = Wb + (mm * 2) * XPL;
                const unsigned short* Wl = Wh + XPL;
                uint32_t bh0, bh1, bh2, bh3, bl0, bl1, bl2, bl3;
                ldsm_x4(smem_u32(&Wh[(wn * 16 + brow) * QP + ks * 16 + bcol]),
                        bh0, bh1, bh2, bh3);
                ldsm_x4(smem_u32(&Wl[(wn * 16 + brow) * QP + ks * 16 + bcol]),
                        bl0, bl1, bl2, bl3);
                #pragma unroll
                for (int ma = 0; ma < 2; ma++) {
                    float* c0 = acc[mm][ma][0];
                    float* c1 = acc[mm][ma][1];
                    mma_bf16(c0, ah[ma][0], ah[ma][1], ah[ma][2], ah[ma][3], bh0, bh1);
                    mma_bf16(c0, ah[ma][0], ah[ma][1], ah[ma][2], ah[ma][3], bl0, bl1);
                    mma_bf16(c0, al[ma][0], al[ma][1], al[ma][2], al[ma][3], bh0, bh1);
                    mma_bf16(c1, ah[ma][0], ah[ma][1], ah[ma][2], ah[ma][3], bh2, bh3);
                    mma_bf16(c1, ah[ma][0], ah[ma][1], ah[ma][2], ah[ma][3], bl2, bl3);
                    mma_bf16(c1, al[ma][0], al[ma][1], al[ma][2], al[ma][3], bh2, bh3);
                }
            }
        }

        // end-of-body wait: ensure W[i+1] landed (each thread, pre-barrier)
        if (i + 1 < NI) {
            if (i + 2 < NI) asm volatile("cp.async.wait_group 1;");
            else            asm volatile("cp.async.wait_group 0;");
        }
    }

    // epilogue: Q (mm=0) scattered; K/V (mm=1,2) compacted. 2Mx4N mapping.
    #pragma unroll
    for (int ma = 0; ma < 2; ma++) {
        int jr0 = j0 + wm * 32 + ma * 16 + (lane >> 2);
        int jr8 = jr0 + 8;
        if (jr0 > cnt - 1) jr0 = cnt - 1;
        if (jr8 > cnt - 1) jr8 = cnt - 1;
        const size_t qrow0 = (size_t)b * SS + list[jr0];
        const size_t qrow8 = (size_t)b * SS + list[jr8];
        #pragma unroll
        for (int mm = 0; mm < NMAT; mm++) {
            const float* bias = (mm == 0) ? bq : (mm == 1) ? bk : bv;
            unsigned int* gh = (mm == 0) ? g_qh : (mm == 1) ? g_kh : g_vh;
            unsigned int* gl = (mm == 0) ? g_ql : (mm == 1) ? g_kl : g_vl;
            size_t r0, r8;
            if (mm == 0) { r0 = qrow0; r8 = qrow8; }
            else {
                r0 = (size_t)b * SS + j0 + wm * 32 + ma * 16 + (lane >> 2);
                r8 = r0 + 8;
            }
            #pragma unroll
            for (int na = 0; na < 2; na++) {
                int col = wn * 16 + na * 8 + (lane & 3) * 2;
                float b0 = bias[col], b1 = bias[col + 1];
                float c0 = acc[mm][ma][na][0] + b0, c1 = acc[mm][ma][na][1] + b1;
                float c2 = acc[mm][ma][na][2] + b0, c3 = acc[mm][ma][na][3] + b1;
                uint32_t h, l;
                split_pair(c0, c1, h, l);
                gh[r0 * 32 + col / 2] = h;
                gl[r0 * 32 + col / 2] = l;
                split_pair(c2, c3, h, l);
                gh[r8 * 32 + col / 2] = h;
                gl[r8 * 32 + col / 2] = l;
            }
        }
    }
}

__global__ __launch_bounds__(256, 2) void proj_kernel(
    const float* __restrict__ x,
    const float* __restrict__ bq, const float* __restrict__ bk,
    const float* __restrict__ bv)
{
    extern __shared__ unsigned short qsm[];
    const int b = blockIdx.y;
    const int j0 = blockIdx.x * 64;
    const int nk = g_kcnt[b];

    if (blockIdx.z == 0) {
        if (j0 >= nk) return;
        proj_body<3>(qsm, x, bq, bk, bv, b, j0, nk, g_kidx[b]);
    } else {
        const int nm = SS - nk;
        if (j0 >= nm || nm == 0) return;
        proj_body<1>(qsm, x, bq, bk, bv, b, j0, nm, g_midx[b]);
    }
}

// ---------------------------------------------------------------------------
// Flash attention, PERSISTENT scheduler (unchanged from champion).
// ---------------------------------------------------------------------------
#define KP 72
#define TILE_U16 (64 * KP)
#define STAGE_U16 (4 * TILE_U16)
#define ATTN_SMEM_BYTES (2 * STAGE_U16 * 2 + 64 * 4)

__device__ __forceinline__ void stage_tile(uint32_t sbase, size_t gbase, int t) {
    #pragma unroll
    for (int i = 0; i < 4; i++) {
        int chunk = t + i * 128;
        int r = chunk >> 3, c = chunk & 7;
        uint32_t soff = (uint32_t)(r * KP + c * 8) * 2;
        size_t goff = (size_t)r * 32 + c * 4;
        cp16(sbase + soff,                     g_kh + gbase + goff);
        cp16(sbase + TILE_U16 * 2 + soff,      g_kl + gbase + goff);
        cp16(sbase + 2 * TILE_U16 * 2 + soff,  g_vh + gbase + goff);
        cp16(sbase + 3 * TILE_U16 * 2 + soff,  g_vl + gbase + goff);
    }
    asm volatile("cp.async.commit_group;");
}

__device__ __forceinline__ void flash_segment(
    unsigned short* sm, float* ms, int b, int q0, int t0, int nt, int nk, int slot)
{
    const int t = threadIdx.x, warp = t >> 5, lane = t & 31;

    __syncthreads();

    {
        uint32_t s0 = smem_u32(sm);
        size_t gq = ((size_t)b * SS + q0) * 32;
        #pragma unroll
        for (int i = 0; i < 4; i++) {
            int chunk = t + i * 128;
            int r = chunk >> 3, c = chunk & 7;
            uint32_t soff = (uint32_t)(r * KP + c * 8) * 2;
            size_t goff = (size_t)r * 32 + c * 4;
            cp16(s0 + soff,                g_qh + gq + goff);
            cp16(s0 + TILE_U16 * 2 + soff, g_ql + gq + goff);
        }
        asm volatile("cp.async.commit_group;");
        asm volatile("cp.async.wait_group 0;");
        __syncthreads();
    }

    uint32_t qh[4][4], ql[4][4];
    {
        const int arow = warp * 16 + (lane & 15);
        const int acol = (lane >> 4) * 8;
        #pragma unroll
        for (int ks = 0; ks < 4; ks++) {
            ldsm_x4(smem_u32(&sm[arow * KP + ks * 16 + acol]),
                    qh[ks][0], qh[ks][1], qh[ks][2], qh[ks][3]);
            ldsm_x4(smem_u32(&sm[TILE_U16 + arow * KP + ks * 16 + acol]),
                    ql[ks][0], ql[ks][1], ql[ks][2], ql[ks][3]);
        }
    }
    __syncthreads();

    float O[8][4] = {};
    float m0r = NEGBIG, m1r = NEGBIG, l0r = 0.f, l1r = 0.f;
    const float scale = 0.125f;

    const uint32_t stage_addr[2] = { smem_u32(sm), smem_u32(sm + STAGE_U16) };

    stage_tile(stage_addr[0], ((size_t)b * SS + t0 * 64) * 32, t);

    const int brow = (lane & 7) + ((lane >> 4) << 3);
    const int bco  = ((lane >> 3) & 1) * 8;
    const int vrow = lane & 15;
    const int vco  = (lane >> 4) * 8;

    for (int it = 0; it < nt; ++it) {
        const int st = it & 1;
        const unsigned short* Kh = sm + st * STAGE_U16;
        const unsigned short* Kl = Kh + TILE_U16;
        const unsigned short* Vh = Kh + 2 * TILE_U16;
        const unsigned short* Vl = Kh + 3 * TILE_U16;

        if (it + 1 < nt)
            stage_tile(stage_addr[st ^ 1], ((size_t)b * SS + (t0 + it + 1) * 64) * 32, t);
        if (t < 64) ms[t] = ((t0 + it) * 64 + t < nk) ? 0.f : NEGBIG;

        if (it + 1 < nt) asm volatile("cp.async.wait_group 1;");
        else             asm volatile("cp.async.wait_group 0;");
        __syncthreads();

        float S[8][4] = {};
        #pragma unroll
        for (int ks = 0; ks < 4; ks++) {
            #pragma unroll
            for (int pr = 0; pr < 4; pr++) {
                uint32_t bh0, bh1, bh2, bh3, bl0, bl1, bl2, bl3;
                ldsm_x4(smem_u32(&Kh[(pr * 16 + brow) * KP + ks * 16 + bco]),
                        bh0, bh1, bh2, bh3);
                ldsm_x4(smem_u32(&Kl[(pr * 16 + brow) * KP + ks * 16 + bco]),
                        bl0, bl1, bl2, bl3);
                float* s0 = S[pr * 2];
                float* s1 = S[pr * 2 + 1];
                mma_bf16(s0, qh[ks][0], qh[ks][1], qh[ks][2], qh[ks][3], bh0, bh1);
                mma_bf16(s0, qh[ks][0], qh[ks][1], qh[ks][2], qh[ks][3], bl0, bl1);
                mma_bf16(s0, ql[ks][0], ql[ks][1], ql[ks][2], ql[ks][3], bh0, bh1);
                mma_bf16(s1, qh[ks][0], qh[ks][1], qh[ks][2], qh[ks][3], bh2, bh3);
                mma_bf16(s1, qh[ks][0], qh[ks][1], qh[ks][2], qh[ks][3], bl2, bl3);
                mma_bf16(s1, ql[ks][0], ql[ks][1], ql[ks][2], ql[ks][3], bh2, bh3);
            }
        }

        float rmax0 = NEGBIG, rmax1 = NEGBIG;
        #pragma unroll
        for (int na = 0; na < 8; na++) {
            int col = na * 8 + (lane & 3) * 2;
            float ma = ms[col], mb = ms[col + 1];
            S[na][0] = S[na][0] * scale + ma;
            S[na][1] = S[na][1] * scale + mb;
            S[na][2] = S[na][2] * scale + ma;
            S[na][3] = S[na][3] * scale + mb;
            rmax0 = fmaxf(rmax0, fmaxf(S[na][0], S[na][1]));
            rmax1 = fmaxf(rmax1, fmaxf(S[na][2], S[na][3]));
        }
        rmax0 = fmaxf(rmax0, __shfl_xor_sync(0xffffffffu, rmax0, 1));
        rmax0 = fmaxf(rmax0, __shfl_xor_sync(0xffffffffu, rmax0, 2));
        rmax1 = fmaxf(rmax1, __shfl_xor_sync(0xffffffffu, rmax1, 1));
        rmax1 = fmaxf(rmax1, __shfl_xor_sync(0xffffffffu, rmax1, 2));

        float nm0 = fmaxf(m0r, rmax0), nm1 = fmaxf(m1r, rmax1);
        float f0 = __expf(m0r - nm0);
        float f1 = __expf(m1r - nm1);
        float rs0 = 0.f, rs1 = 0.f;
        #pragma unroll
        for (int na = 0; na < 8; na++) {
            float p0 = __expf(S[na][0] - nm0);
            float p1 = __expf(S[na][1] - nm0);
            float p2 = __expf(S[na][2] - nm1);
            float p3 = __expf(S[na][3] - nm1);
            S[na][0] = p0; S[na][1] = p1; S[na][2] = p2; S[na][3] = p3;
            rs0 += p0 + p1; rs1 += p2 + p3;
        }
        rs0 += __shfl_xor_sync(0xffffffffu, rs0, 1);
        rs0 += __shfl_xor_sync(0xffffffffu, rs0, 2);
        rs1 += __shfl_xor_sync(0xffffffffu, rs1, 1);
        rs1 += __shfl_xor_sync(0xffffffffu, rs1, 2);
        l0r = l0r * f0 + rs0;  m0r = nm0;
        l1r = l1r * f1 + rs1;  m1r = nm1;

        #pragma unroll
        for (int na = 0; na < 8; na++) {
            O[na][0] *= f0; O[na][1] *= f0;
            O[na][2] *= f1; O[na][3] *= f1;
        }

        #pragma unroll
        for (int kk = 0; kk < 4; kk++) {
            uint32_t ph[4], pl[4];
            split_pair(S[2 * kk][0],     S[2 * kk][1],     ph[0], pl[0]);
            split_pair(S[2 * kk][2],     S[2 * kk][3],     ph[1], pl[1]);
            split_pair(S[2 * kk + 1][0], S[2 * kk + 1][1], ph[2], pl[2]);
            split_pair(S[2 * kk + 1][2], S[2 * kk + 1][3], ph[3], pl[3]);
            #pragma unroll
            for (int pr = 0; pr < 4; pr++) {
                uint32_t bh0, bh1, bh2, bh3, bl0, bl1, bl2, bl3;
                ldsm_x4_t(smem_u32(&Vh[(kk * 16 + vrow) * KP + pr * 16 + vco]),
                          bh0, bh1, bh2, bh3);
                ldsm_x4_t(smem_u32(&Vl[(kk * 16 + vrow) * KP + pr * 16 + vco]),
                          bl0, bl1, bl2, bl3);
                float* o0 = O[pr * 2];
                float* o1 = O[pr * 2 + 1];
                mma_bf16(o0, ph[0], ph[1], ph[2], ph[3], bh0, bh1);
                mma_bf16(o0, ph[0], ph[1], ph[2], ph[3], bl0, bl1);
                mma_bf16(o0, pl[0], pl[1], pl[2], pl[3], bh0, bh1);
                mma_bf16(o1, ph[0], ph[1], ph[2], ph[3], bh2, bh3);
                mma_bf16(o1, ph[0], ph[1], ph[2], ph[3], bl2, bl3);
                mma_bf16(o1, pl[0], pl[1], pl[2], pl[3], bh2, bh3);
            }
        }
        __syncthreads();
    }

    int row0 = q0 + warp * 16 + (lane >> 2);
    float* Op = g_Op[slot];
    #pragma unroll
    for (int na = 0; na < 8; na++) {
        int col = na * 8 + (lane & 3) * 2;
        *(float2*)&Op[((size_t)b * SS + row0) * DD + col] =
            make_float2(O[na][0], O[na][1]);
        *(float2*)&Op[((size_t)b * SS + row0 + 8) * DD + col] =
            make_float2(O[na][2], O[na][3]);
    }
    if ((lane & 3) == 0) {
        size_t r = (size_t)b * SS + row0;
        g_mp[slot][r] = m0r;     g_lp[slot][r] = l0r;
        g_mp[slot][r + 8] = m1r; g_lp[slot][r + 8] = l1r;
    }
}

__global__ __launch_bounds__(128, 3) void attn_kernel()
{
    extern __shared__ unsigned short sm[];
    float* ms = (float*)(sm + 2 * STAGE_U16);

    const int c = blockIdx.x;

    int Tb[BB], cum[BB + 1];
    cum[0] = 0;
    #pragma unroll
    for (int b = 0; b < BB; b++) {
        Tb[b] = (g_kcnt[b] + 63) >> 6;
        cum[b + 1] = cum[b] + 32 * Tb[b];
    }
    const int total = cum[BB];
    const int W = (total + NCTA - 1) / NCTA;

    int g = c * W;
    int g1 = g + W;
    if (g1 > total) g1 = total;

    while (g < g1) {
        int b = 0;
        while (g >= cum[b + 1]) b++;
        const int rel = g - cum[b];
        const int qi = rel / Tb[b];
        const int lt = rel - qi * Tb[b];
        const int P0 = cum[b] + qi * Tb[b];
        int run = Tb[b] - lt;
        if (run > g1 - g) run = g1 - g;
        int slot = c - P0 / W;
        if (slot > NSLOT - 1) slot = NSLOT - 1;   // defensive
        flash_segment(sm, ms, b, qi * 64, lt, run, g_kcnt[b], slot);
        g += run;
    }
}

// ---------------------------------------------------------------------------
// combine split-KV partials (NSLOT-way); zero slots contribute 0 exactly
// ---------------------------------------------------------------------------
__global__ void combine_kernel(float* __restrict__ out) {
    int base = blockIdx.x * 512 + threadIdx.x;
    #pragma unroll
    for (int u = 0; u < 2; u++) {
        int idx = base + u * 256;
        int row = idx >> 4;
        float m[NSLOT], M = NEGBIG;
        #pragma unroll
        for (int s = 0; s < NSLOT; s++) {
            m[s] = g_mp[s][row];
            M = fmaxf(M, m[s]);
        }
        float wgt[NSLOT], denom = 0.f;
        #pragma unroll
        for (int s = 0; s < NSLOT; s++) {
            wgt[s] = __expf(m[s] - M);
            denom += wgt[s] * g_lp[s][row];
        }
        float inv = 1.f / denom;
        float4 r = make_float4(0.f, 0.f, 0.f, 0.f);
        #pragma unroll
        for (int s = 0; s < NSLOT; s++) {
            float a = wgt[s] * inv;
            float4 o = reinterpret_cast<const float4*>(g_Op[s])[idx];
            r.x += o.x * a; r.y += o.y * a; r.z += o.z * a; r.w += o.w * a;
        }
        reinterpret_cast<float4*>(out)[idx] = r;
    }
}

// ---------------------------------------------------------------------------
// Launch
// ---------------------------------------------------------------------------
extern "C" void kernel_launch(void* const* d_in, const int* in_sizes, int n_in,
                              void* d_out, int out_size) {
    const float* x  = (const float*)d_in[0];
    const float* Wq = (const float*)d_in[1];
    const float* bq = (const float*)d_in[2];
    const float* Wk = (const float*)d_in[3];
    const float* bk = (const float*)d_in[4];
    const float* Wv = (const float*)d_in[5];
    const float* bv = (const float*)d_in[6];
    const int*   pm = (const int*)d_in[7];
    float* out = (float*)d_out;

    prep_kernel<<<WBLK + BB, 256>>>(Wq, Wk, Wv, pm);

    cudaFuncSetAttribute(proj_kernel, cudaFuncAttributeMaxDynamicSharedMemorySize,
                         PROJ_SMEM_BYTES);
    proj_kernel<<<dim3(SS / 64, BB, 2), 256, PROJ_SMEM_BYTES>>>(x, bq, bk, bv);

    cudaFuncSetAttribute(attn_kernel, cudaFuncAttributeMaxDynamicSharedMemorySize,
                         ATTN_SMEM_BYTES);
    attn_kernel<<<NCTA, 128, ATTN_SMEM_BYTES>>>();

    combine_kernel<<<BB * SS * DD / 8 / 256, 256>>>(out);
}

// round 17
// speedup vs baseline: 1.1267x; 1.0850x over previous
#include <cuda_runtime.h>
#include <cstdint>
#include <math.h>

#define BB 8
#define SS 2048
#define EE 1024
#define DD 64
#define NSLOT 4             // split-KV partial slots (persistent scheduler)
#define NCTA 444            // persistent attn grid = 148 SMs x 3 CTAs
#define NEGBIG (-1.0e30f)   // finite -inf sentinel
#define WBLK 384            // prep: W-split blocks (3*64*512/256)

// q (all rows, scattered) and k,v (COMPACTED rows) as bf16 hi/lo planes
__device__ unsigned int g_qh[BB * SS * DD / 2];
__device__ unsigned int g_ql[BB * SS * DD / 2];
__device__ unsigned int g_kh[BB * SS * DD / 2];
__device__ unsigned int g_kl[BB * SS * DD / 2];
__device__ unsigned int g_vh[BB * SS * DD / 2];
__device__ unsigned int g_vl[BB * SS * DD / 2];

// W planes (bf16 hi/lo), [mat][n][k/2] u32
__device__ unsigned int g_Wh[3 * 64 * 512];
__device__ unsigned int g_Wl[3 * 64 * 512];

// mask compaction
__device__ int g_kidx[BB][SS];
__device__ int g_midx[BB][SS];
__device__ int g_kcnt[BB];

// split-KV partials (zero-init; unused slots contribute exactly 0 in combine)
__device__ float g_Op[NSLOT][BB * SS * DD];
__device__ float g_mp[NSLOT][BB * SS];
__device__ float g_lp[NSLOT][BB * SS];

// ---------------------------------------------------------------------------
// helpers
// ---------------------------------------------------------------------------
__device__ __forceinline__ uint32_t smem_u32(const void* p) {
    return (uint32_t)__cvta_generic_to_shared(p);
}

__device__ __forceinline__ void ldsm_x4(uint32_t addr, uint32_t& r0, uint32_t& r1,
                                        uint32_t& r2, uint32_t& r3) {
    asm volatile("ldmatrix.sync.aligned.m8n8.x4.shared.b16 {%0,%1,%2,%3}, [%4];"
                 : "=r"(r0), "=r"(r1), "=r"(r2), "=r"(r3) : "r"(addr));
}

__device__ __forceinline__ void ldsm_x4_t(uint32_t addr, uint32_t& r0, uint32_t& r1,
                                          uint32_t& r2, uint32_t& r3) {
    asm volatile("ldmatrix.sync.aligned.m8n8.x4.trans.shared.b16 {%0,%1,%2,%3}, [%4];"
                 : "=r"(r0), "=r"(r1), "=r"(r2), "=r"(r3) : "r"(addr));
}

__device__ __forceinline__ void mma_bf16(float c[4],
                                         uint32_t a0, uint32_t a1, uint32_t a2, uint32_t a3,
                                         uint32_t b0, uint32_t b1) {
    asm volatile("mma.sync.aligned.m16n8k16.row.col.f32.bf16.bf16.f32 "
                 "{%0,%1,%2,%3}, {%4,%5,%6,%7}, {%8,%9}, {%0,%1,%2,%3};"
                 : "+f"(c[0]), "+f"(c[1]), "+f"(c[2]), "+f"(c[3])
                 : "r"(a0), "r"(a1), "r"(a2), "r"(a3), "r"(b0), "r"(b1));
}

__device__ __forceinline__ uint32_t pack2(float x0, float x1) {
    uint32_t h;
    asm("cvt.rn.bf16x2.f32 %0, %1, %2;" : "=r"(h) : "f"(x1), "f"(x0));
    return h;
}

__device__ __forceinline__ void split_pair(float x0, float x1, uint32_t& hi, uint32_t& lo) {
    hi = pack2(x0, x1);
    float h0 = __uint_as_float(hi << 16);
    float h1 = __uint_as_float(hi & 0xffff0000u);
    lo = pack2(x0 - h0, x1 - h1);
}

__device__ __forceinline__ void cp16(uint32_t s, const void* g) {
    asm volatile("cp.async.cg.shared.global [%0], [%1], 16;" :: "r"(s), "l"(g));
}

// ---------------------------------------------------------------------------
// fused prep: blocks < WBLK split W; blocks >= WBLK build per-batch compaction
// ---------------------------------------------------------------------------
__global__ void prep_kernel(const float* __restrict__ Wq, const float* __restrict__ Wk,
                            const float* __restrict__ Wv, const int* __restrict__ mask) {
    if (blockIdx.x < WBLK) {
        int idx = blockIdx.x * 256 + threadIdx.x;   // < 98304 = 3*64*512
        int mat = idx >> 15;
        int off = idx & 32767;
        const float* W = (mat == 0) ? Wq : (mat == 1) ? Wk : Wv;
        float2 v = reinterpret_cast<const float2*>(W)[off];
        uint32_t h, l;
        split_pair(v.x, v.y, h, l);
        g_Wh[idx] = h;
        g_Wl[idx] = l;
        return;
    }
    const int b = blockIdx.x - WBLK;
    const int t = threadIdx.x;
    __shared__ int wsum[8];
    const int* mrow = mask + (size_t)b * SS;

    int um[8], loc[8], cnt = 0;
    #pragma unroll
    for (int j = 0; j < 8; j++) {
        int s = t * 8 + j;
        um[j] = (mrow[s] == 0);
        loc[j] = cnt;
        cnt += um[j];
    }
    const int lane = t & 31, w = t >> 5;
    int inc = cnt;
    #pragma unroll
    for (int off = 1; off < 32; off <<= 1) {
        int n = __shfl_up_sync(0xffffffffu, inc, off);
        if (lane >= off) inc += n;
    }
    if (lane == 31) wsum[w] = inc;
    __syncthreads();
    int wbase = 0;
    #pragma unroll
    for (int i = 0; i < 8; i++)
        if (i < w) wbase += wsum[i];
    const int base = wbase + inc - cnt;
    #pragma unroll
    for (int j = 0; j < 8; j++) {
        int s = t * 8 + j;
        int u = base + loc[j];
        if (um[j]) g_kidx[b][u] = s;
        else       g_midx[b][s - u] = s;
    }
    if (t == 255) g_kcnt[b] = base + cnt;
}

// ---------------------------------------------------------------------------
// Projection. BM=128, BK=64, 512 threads, 1 CTA/SM: per-CTA slab count 16
// (vs 32). Warp layout 4M x 4N (wm: 32-row stripe = 2 m-atoms; wn: 16 cols).
// W planes via 2-stage cp.async; x via f32 register prefetch + bf16 split.
// ---------------------------------------------------------------------------
#define KP2 72                        // u16 pitch (144B rows, 16B-aligned)
#define XPL2 (128 * KP2)              // X plane u16 (18432 B)
#define WPL2 (64 * KP2)               // W plane u16 (9216 B)
#define XS2 (2 * XPL2)                // X stage: hi+lo
#define WB2 (2 * XS2)                 // W base (after 2 X stages)
#define PROJ_SMEM_BYTES ((2 * 2 * XPL2 + 2 * 6 * WPL2) * 2)   // 184320 B

template<int NMAT>
__device__ __forceinline__ void proj_body(
    unsigned short* qsm, const float* __restrict__ x,
    const float* __restrict__ bq, const float* __restrict__ bk,
    const float* __restrict__ bv,
    int b, int j0, int cnt, const int* __restrict__ list)
{
    constexpr int WSTGP = 2 * NMAT;

    const int t = threadIdx.x;
    const int warp = t >> 5, lane = t & 31;
    const int wm = warp >> 2;        // 0..3: rows wm*32 .. +32 (2 m-atoms)
    const int wn = warp & 3;         // 0..3: cols wn*16 .. +16 (2 n-atoms)

    float acc[NMAT][2][2][4] = {};   // [mat][matom][natom][reg]

    const int arow = (lane & 15);
    const int acol = (lane >> 4) * 8;
    const int brow = (lane & 7) + ((lane >> 4) << 3);
    const int bcol = ((lane >> 3) & 1) * 8;

    const int xr = t >> 2;           // 0..127 staged row
    const int xc = (t & 3) * 16;     // f32 col base {0,16,32,48}

    int jg = j0 + xr;
    if (jg > cnt - 1) jg = cnt - 1;
    const float* xrow = x + ((size_t)b * SS + list[jg]) * EE;

    // W stage wst for k-slab: 2*NMAT planes x 512 chunks of 16B
    auto issue_w = [&](int wst, int slab) {
        #pragma unroll
        for (int i = 0; i < 2 * NMAT; i++) {
            int chunk = t + i * 512;
            int p = chunk >> 9, c = chunk & 511;
            int row = c >> 3, c8 = c & 7;
            uint32_t dst = smem_u32(&qsm[WB2 + (wst * WSTGP + p) * WPL2 + row * KP2 + c8 * 8]);
            const unsigned int* srcp = (p & 1) ? g_Wl : g_Wh;
            cp16(dst, srcp + ((size_t)(p >> 1) * 32768
                              + (size_t)row * 512 + slab * 32 + c8 * 4));
        }
        asm volatile("cp.async.commit_group;");
    };

    // X stage: 16 f32 -> 8+8 u32 planes, 4 x STS.128
    auto sts_x = [&](int xst, const float4* a) {
        unsigned short* Xh = qsm + xst * XS2;
        unsigned short* Xl = Xh + XPL2;
        #pragma unroll
        for (int q = 0; q < 2; q++) {
            uint32_t h0, l0, h1, l1, h2, l2, h3, l3;
            split_pair(a[2 * q].x,     a[2 * q].y,     h0, l0);
            split_pair(a[2 * q].z,     a[2 * q].w,     h1, l1);
            split_pair(a[2 * q + 1].x, a[2 * q + 1].y, h2, l2);
            split_pair(a[2 * q + 1].z, a[2 * q + 1].w, h3, l3);
            *reinterpret_cast<uint4*>(&Xh[xr * KP2 + xc + q * 8]) = make_uint4(h0, h1, h2, h3);
            *reinterpret_cast<uint4*>(&Xl[xr * KP2 + xc + q * 8]) = make_uint4(l0, l1, l2, l3);
        }
    };

    const int NI = EE / 64;   // 16 slabs

    // prologue: W0 in flight; X0 staged directly; x regs hold slab 1
    issue_w(0, 0);
    {
        float4 a[4];
        #pragma unroll
        for (int q = 0; q < 4; q++)
            a[q] = *reinterpret_cast<const float4*>(&xrow[xc + q * 4]);
        sts_x(0, a);
    }
    float4 xa[4];
    #pragma unroll
    for (int q = 0; q < 4; q++)
        xa[q] = *reinterpret_cast<const float4*>(&xrow[64 + xc + q * 4]);

    for (int i = 0; i < NI; i++) {
        const int s = i & 1;

        asm volatile("cp.async.wait_group 0;");
        __syncthreads();

        if (i + 1 < NI) {
            issue_w(s ^ 1, i + 1);
            sts_x(s ^ 1, xa);
            if (i + 2 < NI) {
                int kn = (i + 2) * 64;
                #pragma unroll
                for (int q = 0; q < 4; q++)
                    xa[q] = *reinterpret_cast<const float4*>(&xrow[kn + xc + q * 4]);
            }
        }

        const unsigned short* Xh = qsm + s * XS2;
        const unsigned short* Xl = Xh + XPL2;
        const unsigned short* Wb = qsm + WB2 + s * WSTGP * WPL2;

        #pragma unroll
        for (int ks = 0; ks < 4; ks++) {
            uint32_t ah[2][4], al[2][4];
            #pragma unroll
            for (int ma = 0; ma < 2; ma++) {
                int r = wm * 32 + ma * 16 + arow;
                ldsm_x4(smem_u32(&Xh[r * KP2 + ks * 16 + acol]),
                        ah[ma][0], ah[ma][1], ah[ma][2], ah[ma][3]);
                ldsm_x4(smem_u32(&Xl[r * KP2 + ks * 16 + acol]),
                        al[ma][0], al[ma][1], al[ma][2], al[ma][3]);
            }
            #pragma unroll
            for (int mm = 0; mm < NMAT; mm++) {
                const unsigned short* Wh = Wb + (mm * 2) * WPL2;
                const unsigned short* Wl = Wh + WPL2;
                uint32_t bh0, bh1, bh2, bh3, bl0, bl1, bl2, bl3;
                ldsm_x4(smem_u32(&Wh[(wn * 16 + brow) * KP2 + ks * 16 + bcol]),
                        bh0, bh1, bh2, bh3);
                ldsm_x4(smem_u32(&Wl[(wn * 16 + brow) * KP2 + ks * 16 + bcol]),
                        bl0, bl1, bl2, bl3);
                #pragma unroll
                for (int ma = 0; ma < 2; ma++) {
                    float* c0 = acc[mm][ma][0];
                    float* c1 = acc[mm][ma][1];
                    mma_bf16(c0, ah[ma][0], ah[ma][1], ah[ma][2], ah[ma][3], bh0, bh1);
                    mma_bf16(c0, ah[ma][0], ah[ma][1], ah[ma][2], ah[ma][3], bl0, bl1);
                    mma_bf16(c0, al[ma][0], al[ma][1], al[ma][2], al[ma][3], bh0, bh1);
                    mma_bf16(c1, ah[ma][0], ah[ma][1], ah[ma][2], ah[ma][3], bh2, bh3);
                    mma_bf16(c1, ah[ma][0], ah[ma][1], ah[ma][2], ah[ma][3], bl2, bl3);
                    mma_bf16(c1, al[ma][0], al[ma][1], al[ma][2], al[ma][3], bh2, bh3);
                }
            }
        }
    }

    // epilogue: Q (mm=0) scattered; K/V (mm=1,2) compacted. 4Mx4N mapping.
    #pragma unroll
    for (int ma = 0; ma < 2; ma++) {
        int jr0 = j0 + wm * 32 + ma * 16 + (lane >> 2);
        int jr8 = jr0 + 8;
        if (jr0 > cnt - 1) jr0 = cnt - 1;
        if (jr8 > cnt - 1) jr8 = cnt - 1;
        const size_t qrow0 = (size_t)b * SS + list[jr0];
        const size_t qrow8 = (size_t)b * SS + list[jr8];
        #pragma unroll
        for (int mm = 0; mm < NMAT; mm++) {
            const float* bias = (mm == 0) ? bq : (mm == 1) ? bk : bv;
            unsigned int* gh = (mm == 0) ? g_qh : (mm == 1) ? g_kh : g_vh;
            unsigned int* gl = (mm == 0) ? g_ql : (mm == 1) ? g_kl : g_vl;
            size_t r0, r8;
            if (mm == 0) { r0 = qrow0; r8 = qrow8; }
            else {
                r0 = (size_t)b * SS + j0 + wm * 32 + ma * 16 + (lane >> 2);
                r8 = r0 + 8;
            }
            #pragma unroll
            for (int na = 0; na < 2; na++) {
                int col = wn * 16 + na * 8 + (lane & 3) * 2;
                float b0 = bias[col], b1 = bias[col + 1];
                float c0 = acc[mm][ma][na][0] + b0, c1 = acc[mm][ma][na][1] + b1;
                float c2 = acc[mm][ma][na][2] + b0, c3 = acc[mm][ma][na][3] + b1;
                uint32_t h, l;
                split_pair(c0, c1, h, l);
                gh[r0 * 32 + col / 2] = h;
                gl[r0 * 32 + col / 2] = l;
                split_pair(c2, c3, h, l);
                gh[r8 * 32 + col / 2] = h;
                gl[r8 * 32 + col / 2] = l;
            }
        }
    }
}

__global__ __launch_bounds__(512, 1) void proj_kernel(
    const float* __restrict__ x,
    const float* __restrict__ bq, const float* __restrict__ bk,
    const float* __restrict__ bv)
{
    extern __shared__ unsigned short qsm[];
    const int b = blockIdx.y;
    const int j0 = blockIdx.x * 128;
    const int nk = g_kcnt[b];

    if (blockIdx.z == 0) {
        if (j0 >= nk) return;
        proj_body<3>(qsm, x, bq, bk, bv, b, j0, nk, g_kidx[b]);
    } else {
        const int nm = SS - nk;
        if (j0 >= nm || nm == 0) return;
        proj_body<1>(qsm, x, bq, bk, bv, b, j0, nm, g_midx[b]);
    }
}

// ---------------------------------------------------------------------------
// Flash attention, PERSISTENT scheduler (unchanged from champion).
// ---------------------------------------------------------------------------
#define KP 72
#define TILE_U16 (64 * KP)
#define STAGE_U16 (4 * TILE_U16)
#define ATTN_SMEM_BYTES (2 * STAGE_U16 * 2 + 64 * 4)

__device__ __forceinline__ void stage_tile(uint32_t sbase, size_t gbase, int t) {
    #pragma unroll
    for (int i = 0; i < 4; i++) {
        int chunk = t + i * 128;
        int r = chunk >> 3, c = chunk & 7;
        uint32_t soff = (uint32_t)(r * KP + c * 8) * 2;
        size_t goff = (size_t)r * 32 + c * 4;
        cp16(sbase + soff,                     g_kh + gbase + goff);
        cp16(sbase + TILE_U16 * 2 + soff,      g_kl + gbase + goff);
        cp16(sbase + 2 * TILE_U16 * 2 + soff,  g_vh + gbase + goff);
        cp16(sbase + 3 * TILE_U16 * 2 + soff,  g_vl + gbase + goff);
    }
    asm volatile("cp.async.commit_group;");
}

__device__ __forceinline__ void flash_segment(
    unsigned short* sm, float* ms, int b, int q0, int t0, int nt, int nk, int slot)
{
    const int t = threadIdx.x, warp = t >> 5, lane = t & 31;

    __syncthreads();

    {
        uint32_t s0 = smem_u32(sm);
        size_t gq = ((size_t)b * SS + q0) * 32;
        #pragma unroll
        for (int i = 0; i < 4; i++) {
            int chunk = t + i * 128;
            int r = chunk >> 3, c = chunk & 7;
            uint32_t soff = (uint32_t)(r * KP + c * 8) * 2;
            size_t goff = (size_t)r * 32 + c * 4;
            cp16(s0 + soff,                g_qh + gq + goff);
            cp16(s0 + TILE_U16 * 2 + soff, g_ql + gq + goff);
        }
        asm volatile("cp.async.commit_group;");
        asm volatile("cp.async.wait_group 0;");
        __syncthreads();
    }

    uint32_t qh[4][4], ql[4][4];
    {
        const int arow = warp * 16 + (lane & 15);
        const int acol = (lane >> 4) * 8;
        #pragma unroll
        for (int ks = 0; ks < 4; ks++) {
            ldsm_x4(smem_u32(&sm[arow * KP + ks * 16 + acol]),
                    qh[ks][0], qh[ks][1], qh[ks][2], qh[ks][3]);
            ldsm_x4(smem_u32(&sm[TILE_U16 + arow * KP + ks * 16 + acol]),
                    ql[ks][0], ql[ks][1], ql[ks][2], ql[ks][3]);
        }
    }
    __syncthreads();

    float O[8][4] = {};
    float m0r = NEGBIG, m1r = NEGBIG, l0r = 0.f, l1r = 0.f;
    const float scale = 0.125f;

    const uint32_t stage_addr[2] = { smem_u32(sm), smem_u32(sm + STAGE_U16) };

    stage_tile(stage_addr[0], ((size_t)b * SS + t0 * 64) * 32, t);

    const int brow = (lane & 7) + ((lane >> 4) << 3);
    const int bco  = ((lane >> 3) & 1) * 8;
    const int vrow = lane & 15;
    const int vco  = (lane >> 4) * 8;

    for (int it = 0; it < nt; ++it) {
        const int st = it & 1;
        const unsigned short* Kh = sm + st * STAGE_U16;
        const unsigned short* Kl = Kh + TILE_U16;
        const unsigned short* Vh = Kh + 2 * TILE_U16;
        const unsigned short* Vl = Kh + 3 * TILE_U16;

        if (it + 1 < nt)
            stage_tile(stage_addr[st ^ 1], ((size_t)b * SS + (t0 + it + 1) * 64) * 32, t);
        if (t < 64) ms[t] = ((t0 + it) * 64 + t < nk) ? 0.f : NEGBIG;

        if (it + 1 < nt) asm volatile("cp.async.wait_group 1;");
        else             asm volatile("cp.async.wait_group 0;");
        __syncthreads();

        float S[8][4] = {};
        #pragma unroll
        for (int ks = 0; ks < 4; ks++) {
            #pragma unroll
            for (int pr = 0; pr < 4; pr++) {
                uint32_t bh0, bh1, bh2, bh3, bl0, bl1, bl2, bl3;
                ldsm_x4(smem_u32(&Kh[(pr * 16 + brow) * KP + ks * 16 + bco]),
                        bh0, bh1, bh2, bh3);
                ldsm_x4(smem_u32(&Kl[(pr * 16 + brow) * KP + ks * 16 + bco]),
                        bl0, bl1, bl2, bl3);
                float* s0 = S[pr * 2];
                float* s1 = S[pr * 2 + 1];
                mma_bf16(s0, qh[ks][0], qh[ks][1], qh[ks][2], qh[ks][3], bh0, bh1);
                mma_bf16(s0, qh[ks][0], qh[ks][1], qh[ks][2], qh[ks][3], bl0, bl1);
                mma_bf16(s0, ql[ks][0], ql[ks][1], ql[ks][2], ql[ks][3], bh0, bh1);
                mma_bf16(s1, qh[ks][0], qh[ks][1], qh[ks][2], qh[ks][3], bh2, bh3);
                mma_bf16(s1, qh[ks][0], qh[ks][1], qh[ks][2], qh[ks][3], bl2, bl3);
                mma_bf16(s1, ql[ks][0], ql[ks][1], ql[ks][2], ql[ks][3], bh2, bh3);
            }
        }

        float rmax0 = NEGBIG, rmax1 = NEGBIG;
        #pragma unroll
        for (int na = 0; na < 8; na++) {
            int col = na * 8 + (lane & 3) * 2;
            float ma = ms[col], mb = ms[col + 1];
            S[na][0] = S[na][0] * scale + ma;
            S[na][1] = S[na][1] * scale + mb;
            S[na][2] = S[na][2] * scale + ma;
            S[na][3] = S[na][3] * scale + mb;
            rmax0 = fmaxf(rmax0, fmaxf(S[na][0], S[na][1]));
            rmax1 = fmaxf(rmax1, fmaxf(S[na][2], S[na][3]));
        }
        rmax0 = fmaxf(rmax0, __shfl_xor_sync(0xffffffffu, rmax0, 1));
        rmax0 = fmaxf(rmax0, __shfl_xor_sync(0xffffffffu, rmax0, 2));
        rmax1 = fmaxf(rmax1, __shfl_xor_sync(0xffffffffu, rmax1, 1));
        rmax1 = fmaxf(rmax1, __shfl_xor_sync(0xffffffffu, rmax1, 2));

        float nm0 = fmaxf(m0r, rmax0), nm1 = fmaxf(m1r, rmax1);
        float f0 = __expf(m0r - nm0);
        float f1 = __expf(m1r - nm1);
        float rs0 = 0.f, rs1 = 0.f;
        #pragma unroll
        for (int na = 0; na < 8; na++) {
            float p0 = __expf(S[na][0] - nm0);
            float p1 = __expf(S[na][1] - nm0);
            float p2 = __expf(S[na][2] - nm1);
            float p3 = __expf(S[na][3] - nm1);
            S[na][0] = p0; S[na][1] = p1; S[na][2] = p2; S[na][3] = p3;
            rs0 += p0 + p1; rs1 += p2 + p3;
        }
        rs0 += __shfl_xor_sync(0xffffffffu, rs0, 1);
        rs0 += __shfl_xor_sync(0xffffffffu, rs0, 2);
        rs1 += __shfl_xor_sync(0xffffffffu, rs1, 1);
        rs1 += __shfl_xor_sync(0xffffffffu, rs1, 2);
        l0r = l0r * f0 + rs0;  m0r = nm0;
        l1r = l1r * f1 + rs1;  m1r = nm1;

        #pragma unroll
        for (int na = 0; na < 8; na++) {
            O[na][0] *= f0; O[na][1] *= f0;
            O[na][2] *= f1; O[na][3] *= f1;
        }

        #pragma unroll
        for (int kk = 0; kk < 4; kk++) {
            uint32_t ph[4], pl[4];
            split_pair(S[2 * kk][0],     S[2 * kk][1],     ph[0], pl[0]);
            split_pair(S[2 * kk][2],     S[2 * kk][3],     ph[1], pl[1]);
            split_pair(S[2 * kk + 1][0], S[2 * kk + 1][1], ph[2], pl[2]);
            split_pair(S[2 * kk + 1][2], S[2 * kk + 1][3], ph[3], pl[3]);
            #pragma unroll
            for (int pr = 0; pr < 4; pr++) {
                uint32_t bh0, bh1, bh2, bh3, bl0, bl1, bl2, bl3;
                ldsm_x4_t(smem_u32(&Vh[(kk * 16 + vrow) * KP + pr * 16 + vco]),
                          bh0, bh1, bh2, bh3);
                ldsm_x4_t(smem_u32(&Vl[(kk * 16 + vrow) * KP + pr * 16 + vco]),
                          bl0, bl1, bl2, bl3);
                float* o0 = O[pr * 2];
                float* o1 = O[pr * 2 + 1];
                mma_bf16(o0, ph[0], ph[1], ph[2], ph[3], bh0, bh1);
                mma_bf16(o0, ph[0], ph[1], ph[2], ph[3], bl0, bl1);
                mma_bf16(o0, pl[0], pl[1], pl[2], pl[3], bh0, bh1);
                mma_bf16(o1, ph[0], ph[1], ph[2], ph[3], bh2, bh3);
                mma_bf16(o1, ph[0], ph[1], ph[2], ph[3], bl2, bl3);
                mma_bf16(o1, pl[0], pl[1], pl[2], pl[3], bh2, bh3);
            }
        }
        __syncthreads();
    }

    int row0 = q0 + warp * 16 + (lane >> 2);
    float* Op = g_Op[slot];
    #pragma unroll
    for (int na = 0; na < 8; na++) {
        int col = na * 8 + (lane & 3) * 2;
        *(float2*)&Op[((size_t)b * SS + row0) * DD + col] =
            make_float2(O[na][0], O[na][1]);
        *(float2*)&Op[((size_t)b * SS + row0 + 8) * DD + col] =
            make_float2(O[na][2], O[na][3]);
    }
    if ((lane & 3) == 0) {
        size_t r = (size_t)b * SS + row0;
        g_mp[slot][r] = m0r;     g_lp[slot][r] = l0r;
        g_mp[slot][r + 8] = m1r; g_lp[slot][r + 8] = l1r;
    }
}

__global__ __launch_bounds__(128, 3) void attn_kernel()
{
    extern __shared__ unsigned short sm[];
    float* ms = (float*)(sm + 2 * STAGE_U16);

    const int c = blockIdx.x;

    int Tb[BB], cum[BB + 1];
    cum[0] = 0;
    #pragma unroll
    for (int b = 0; b < BB; b++) {
        Tb[b] = (g_kcnt[b] + 63) >> 6;
        cum[b + 1] = cum[b] + 32 * Tb[b];
    }
    const int total = cum[BB];
    const int W = (total + NCTA - 1) / NCTA;

    int g = c * W;
    int g1 = g + W;
    if (g1 > total) g1 = total;

    while (g < g1) {
        int b = 0;
        while (g >= cum[b + 1]) b++;
        const int rel = g - cum[b];
        const int qi = rel / Tb[b];
        const int lt = rel - qi * Tb[b];
        const int P0 = cum[b] + qi * Tb[b];
        int run = Tb[b] - lt;
        if (run > g1 - g) run = g1 - g;
        int slot = c - P0 / W;
        if (slot > NSLOT - 1) slot = NSLOT - 1;   // defensive
        flash_segment(sm, ms, b, qi * 64, lt, run, g_kcnt[b], slot);
        g += run;
    }
}

// ---------------------------------------------------------------------------
// combine split-KV partials; slots with l==0 contribute nothing -> skip O load
// ---------------------------------------------------------------------------
__global__ void combine_kernel(float* __restrict__ out) {
    int base = blockIdx.x * 512 + threadIdx.x;
    #pragma unroll
    for (int u = 0; u < 2; u++) {
        int idx = base + u * 256;
        int row = idx >> 4;
        float m[NSLOT], lsum[NSLOT], M = NEGBIG;
        #pragma unroll
        for (int s = 0; s < NSLOT; s++) {
            m[s] = g_mp[s][row];
            lsum[s] = g_lp[s][row];
            M = fmaxf(M, m[s]);
        }
        float wgt[NSLOT], denom = 0.f;
        #pragma unroll
        for (int s = 0; s < NSLOT; s++) {
            wgt[s] = __expf(m[s] - M);
            denom += wgt[s] * lsum[s];
        }
        float inv = 1.f / denom;
        float4 r = make_float4(0.f, 0.f, 0.f, 0.f);
        #pragma unroll
        for (int s = 0; s < NSLOT; s++) {
            if (lsum[s] != 0.f) {
                float a = wgt[s] * inv;
                float4 o = reinterpret_cast<const float4*>(g_Op[s])[idx];
                r.x += o.x * a; r.y += o.y * a; r.z += o.z * a; r.w += o.w * a;
            }
        }
        reinterpret_cast<float4*>(out)[idx] = r;
    }
}

// ---------------------------------------------------------------------------
// Launch
// ---------------------------------------------------------------------------
extern "C" void kernel_launch(void* const* d_in, const int* in_sizes, int n_in,
                              void* d_out, int out_size) {
    const float* x  = (const float*)d_in[0];
    const float* Wq = (const float*)d_in[1];
    const float* bq = (const float*)d_in[2];
    const float* Wk = (const float*)d_in[3];
    const float* bk = (const float*)d_in[4];
    const float* Wv = (const float*)d_in[5];
    const float* bv = (const float*)d_in[6];
    const int*   pm = (const int*)d_in[7];
    float* out = (float*)d_out;

    prep_kernel<<<WBLK + BB, 256>>>(Wq, Wk, Wv, pm);

    cudaFuncSetAttribute(proj_kernel, cudaFuncAttributeMaxDynamicSharedMemorySize,
                         PROJ_SMEM_BYTES);
    proj_kernel<<<dim3(SS / 128, BB, 2), 512, PROJ_SMEM_BYTES>>>(x, bq, bk, bv);

    cudaFuncSetAttribute(attn_kernel, cudaFuncAttributeMaxDynamicSharedMemorySize,
                         ATTN_SMEM_BYTES);
    attn_kernel<<<NCTA, 128, ATTN_SMEM_BYTES>>>();

    combine_kernel<<<BB * SS * DD / 8 / 256, 256>>>(out);
}